// round 7
// baseline (speedup 1.0000x reference)
#include <cuda_runtime.h>
#include <cuda_bf16.h>
#include <cmath>
#include <cstdint>

#define N_TOK 4096
#define E_DIM 512
#define NH 8
#define DK 64
#define WSZ 128
#define NBLK 32
#define NDIMS 16
#define QKV_LD 1536
#define CHUNKS 64
#define CLEN 64
#define KDIM 512

// ---------------- scratch (device globals) ----------------
__device__ float g_qkv [N_TOK * QKV_LD];
__device__ float g_attn[N_TOK * E_DIM];
__device__ float g_cema[N_TOK * E_DIM];
__device__ float g_hend [CHUNKS * E_DIM * NDIMS];
__device__ float g_carry[CHUNKS * E_DIM * NDIMS];
__device__ float g_sv[E_DIM];
__device__ float g_absmax[4];     // 0=x, 1=Wqkv, 2=Wout, 3=attn_out
__device__ int8_t g_x1 [N_TOK * E_DIM];
__device__ int8_t g_x2 [N_TOK * E_DIM];
__device__ int8_t g_a1 [N_TOK * E_DIM];
__device__ int8_t g_a2 [N_TOK * E_DIM];
__device__ int8_t g_wq1[QKV_LD * E_DIM];
__device__ int8_t g_wq2[QKV_LD * E_DIM];
__device__ int8_t g_wo1[E_DIM * E_DIM];
__device__ int8_t g_wo2[E_DIM * E_DIM];

// ---------------- PTX helpers ----------------
__device__ __forceinline__ uint32_t smem_u32(const void* p) {
    uint32_t a;
    asm("{ .reg .u64 t; cvta.to.shared.u64 t, %1; cvt.u32.u64 %0, t; }" : "=r"(a) : "l"(p));
    return a;
}
__device__ __forceinline__ void ldsm_x4(uint32_t* r, uint32_t addr) {
    asm volatile("ldmatrix.sync.aligned.m8n8.x4.shared.b16 {%0,%1,%2,%3}, [%4];"
        : "=r"(r[0]), "=r"(r[1]), "=r"(r[2]), "=r"(r[3]) : "r"(addr));
}
__device__ __forceinline__ void ldsm_x2(uint32_t* r, uint32_t addr) {
    asm volatile("ldmatrix.sync.aligned.m8n8.x2.shared.b16 {%0,%1}, [%2];"
        : "=r"(r[0]), "=r"(r[1]) : "r"(addr));
}
__device__ __forceinline__ void imma(int* d, const uint32_t* a, const uint32_t* b) {
    asm volatile("mma.sync.aligned.m16n8k32.row.col.s32.s8.s8.s32 "
        "{%0,%1,%2,%3}, {%4,%5,%6,%7}, {%8,%9}, {%0,%1,%2,%3};"
        : "+r"(d[0]), "+r"(d[1]), "+r"(d[2]), "+r"(d[3])
        : "r"(a[0]), "r"(a[1]), "r"(a[2]), "r"(a[3]), "r"(b[0]), "r"(b[1]));
}
#define CP_ASYNC16(dst, src) \
    asm volatile("cp.async.cg.shared.global [%0], [%1], 16;" :: "r"(dst), "l"(src))
#define CP_COMMIT()  asm volatile("cp.async.commit_group;" ::: "memory")
#define CP_WAIT_1()  asm volatile("cp.async.wait_group 1;" ::: "memory")
#define CP_WAIT_0()  asm volatile("cp.async.wait_group 0;" ::: "memory")

// ---------------- absmax reduction ----------------
__global__ void absmax_kernel(const float4* __restrict__ p, int n4, float* __restrict__ out)
{
    float m = 0.f;
    for (int i = blockIdx.x * blockDim.x + threadIdx.x; i < n4; i += gridDim.x * blockDim.x) {
        float4 v = p[i];
        m = fmaxf(m, fmaxf(fmaxf(fabsf(v.x), fabsf(v.y)), fmaxf(fabsf(v.z), fabsf(v.w))));
    }
#pragma unroll
    for (int s = 16; s > 0; s >>= 1)
        m = fmaxf(m, __shfl_xor_sync(0xFFFFFFFF, m, s));
    if ((threadIdx.x & 31) == 0)
        atomicMax((int*)out, __float_as_int(m));   // values >= 0: int compare valid
}

// ---------------- two-level int8 quantization ----------------
__device__ __forceinline__ void quant2(float x, float inv1, float d1, float inv2,
                                       int8_t& o1, int8_t& o2)
{
    int a1 = __float2int_rn(x * inv1);
    a1 = max(-127, min(127, a1));
    float res = x - (float)a1 * d1;
    int a2 = __float2int_rn(res * inv2);
    a2 = max(-127, min(127, a2));
    o1 = (int8_t)a1;
    o2 = (int8_t)a2;
}

__global__ void conv_q8(const float4* __restrict__ X, const float* __restrict__ mx,
                        int8_t* __restrict__ O1, int8_t* __restrict__ O2)
{
    const float m = mx[0];
    const float d1 = m * (1.f / 127.f);
    const float inv1 = 127.f / m;
    const float inv2 = 254.f / d1;
    const int i = blockIdx.x * blockDim.x + threadIdx.x;
    float4 v = X[i];
    char4 c1, c2;
    quant2(v.x, inv1, d1, inv2, (int8_t&)c1.x, (int8_t&)c2.x);
    quant2(v.y, inv1, d1, inv2, (int8_t&)c1.y, (int8_t&)c2.y);
    quant2(v.z, inv1, d1, inv2, (int8_t&)c1.z, (int8_t&)c2.z);
    quant2(v.w, inv1, d1, inv2, (int8_t&)c1.w, (int8_t&)c2.w);
    ((char4*)O1)[i] = c1;
    ((char4*)O2)[i] = c2;
}

// W [Kdim x Ndim] fp32 -> WT [Ndim x Kdim] two-level int8
__global__ void transpose_conv_q8(const float* __restrict__ W, const float* __restrict__ mx,
                                  int8_t* __restrict__ T1, int8_t* __restrict__ T2,
                                  int Kdim, int Ndim)
{
    __shared__ float t[32][33];
    const float m = mx[0];
    const float d1 = m * (1.f / 127.f);
    const float inv1 = 127.f / m;
    const float inv2 = 254.f / d1;
    const int n0 = blockIdx.x * 32, k0 = blockIdx.y * 32;
    const int tx = threadIdx.x, ty = threadIdx.y;
#pragma unroll
    for (int s = 0; s < 32; s += 8)
        t[ty + s][tx] = W[(k0 + ty + s) * Ndim + n0 + tx];
    __syncthreads();
#pragma unroll
    for (int s = 0; s < 32; s += 8) {
        float v = t[tx][ty + s];
        int8_t o1, o2;
        quant2(v, inv1, d1, inv2, o1, o2);
        T1[(n0 + ty + s) * Kdim + k0 + tx] = o1;
        T2[(n0 + ty + s) * Kdim + k0 + tx] = o2;
    }
}

// ---------------- two-level int8 IMMA GEMM ----------------
// CTA 64(M) x 128(N), 256 thr = 8 warps (2m x 4n), warp 32x32 via m16n8k32.
// K-chunk 64 (bytes), 2-stage cp.async pipeline.
// D = d1A*d1B*(P + Q/254) + bias [mode 0];  mode 1 adds adaptive cema combine.
#define KC 64
#define NCH (KDIM / KC)
#define LDSB 80
#define ST_A1 0
#define ST_A2 5120
#define ST_B1 10240
#define ST_B2 20480
#define STAGE_B 30720
#define GEMM_SMEM_BYTES (2 * STAGE_B)

__device__ __forceinline__ void gemm_load_chunk(
    uint32_t stage_sb, const int8_t* A1, const int8_t* A2,
    const int8_t* B1, const int8_t* B2, int m0, int n0, int kb, int tid)
{
    {   // A: 64 rows x 4 x 16B segs
        const int r = tid >> 2, seg = tid & 3;
        const uint32_t so = stage_sb + (uint32_t)(r * LDSB + seg * 16);
        const int ga = (m0 + r) * KDIM + kb + seg * 16;
        CP_ASYNC16(so + ST_A1, A1 + ga);
        CP_ASYNC16(so + ST_A2, A2 + ga);
    }
#pragma unroll
    for (int i = 0; i < 2; i++) {   // B: 128 rows x 4 segs
        const int idx = tid + i * 256;
        const int r = idx >> 2, seg = idx & 3;
        const uint32_t so = stage_sb + (uint32_t)(r * LDSB + seg * 16);
        const int gb = (n0 + r) * KDIM + kb + seg * 16;
        CP_ASYNC16(so + ST_B1, B1 + gb);
        CP_ASYNC16(so + ST_B2, B2 + gb);
    }
}

__global__ void __launch_bounds__(256, 2)
gemm_imma(const int8_t* __restrict__ A1, const int8_t* __restrict__ A2,
          const int8_t* __restrict__ B1, const int8_t* __restrict__ B2,
          const float* __restrict__ sAp, const float* __restrict__ sBp,
          const float* __restrict__ bias, float* __restrict__ C, int ldc, int mode,
          const float* __restrict__ cema, const float* __restrict__ aw)
{
    extern __shared__ __align__(16) char smem[];
    const uint32_t sb = smem_u32(smem);
    const int tid = threadIdx.x;
    const int wid = tid >> 5, lane = tid & 31;
    const int wm = wid & 1, wn = wid >> 1;           // 2m x 4n warps
    const int m0 = blockIdx.y * 64, n0 = blockIdx.x * 128;

    // ldmatrix lane offsets (same pointer scheme as bf16; s8 fragments match)
    const uint32_t a_off = (uint32_t)(wm * 32 + (lane & 15)) * LDSB + ((lane >> 4) << 4);
    const uint32_t b_off = (uint32_t)(wn * 32 + (lane & 7)) * LDSB + (((lane >> 3) & 1) << 4);

    int P[2][4][4], Q[2][4][4];
#pragma unroll
    for (int mt = 0; mt < 2; mt++)
#pragma unroll
        for (int nt = 0; nt < 4; nt++)
#pragma unroll
            for (int c = 0; c < 4; c++) { P[mt][nt][c] = 0; Q[mt][nt][c] = 0; }

    gemm_load_chunk(sb, A1, A2, B1, B2, m0, n0, 0, tid);
    CP_COMMIT();

    for (int ch = 0; ch < NCH; ch++) {
        const uint32_t st = sb + (uint32_t)((ch & 1) * STAGE_B);
        if (ch + 1 < NCH) {
            gemm_load_chunk(sb + (uint32_t)(((ch + 1) & 1) * STAGE_B),
                            A1, A2, B1, B2, m0, n0, (ch + 1) * KC, tid);
            CP_COMMIT();
            CP_WAIT_1();
        } else {
            CP_WAIT_0();
        }
        __syncthreads();

#pragma unroll
        for (int ks = 0; ks < 2; ks++) {
            const uint32_t kofs = ks * 32;           // k32 step = 32 bytes
            uint32_t a1f[2][4], a2f[2][4];
#pragma unroll
            for (int mt = 0; mt < 2; mt++) {
                ldsm_x4(a1f[mt], st + ST_A1 + a_off + mt * (16 * LDSB) + kofs);
                ldsm_x4(a2f[mt], st + ST_A2 + a_off + mt * (16 * LDSB) + kofs);
            }
#pragma unroll
            for (int nt = 0; nt < 4; nt++) {
                uint32_t b1f[2], b2f[2];
                ldsm_x2(b1f, st + ST_B1 + b_off + nt * (8 * LDSB) + kofs);
                ldsm_x2(b2f, st + ST_B2 + b_off + nt * (8 * LDSB) + kofs);
#pragma unroll
                for (int mt = 0; mt < 2; mt++) {
                    imma(P[mt][nt], a1f[mt], b1f);
                    imma(Q[mt][nt], a1f[mt], b2f);
                    imma(Q[mt][nt], a2f[mt], b1f);
                }
            }
        }
        __syncthreads();
    }

    const float S = (sAp[0] * (1.f / 127.f)) * (sBp[0] * (1.f / 127.f));
    float w0 = 1.f, w1 = 0.f;
    if (mode == 1) {
        float a0 = aw[0], a1 = aw[1];
        float mx = fmaxf(a0, a1);
        float e0 = expf(a0 - mx), e1 = expf(a1 - mx);
        float inv = 1.f / (e0 + e1);
        w0 = e0 * inv; w1 = e1 * inv;
    }

#pragma unroll
    for (int mt = 0; mt < 2; mt++) {
        const int r0 = m0 + wm * 32 + mt * 16 + (lane >> 2);
#pragma unroll
        for (int nt = 0; nt < 4; nt++) {
            const int col = n0 + wn * 32 + nt * 8 + (lane & 3) * 2;
            const float b0v = bias[col], b1v = bias[col + 1];
            float2 v0, v1;
            v0.x = S * ((float)P[mt][nt][0] + (float)Q[mt][nt][0] * (1.f / 254.f)) + b0v;
            v0.y = S * ((float)P[mt][nt][1] + (float)Q[mt][nt][1] * (1.f / 254.f)) + b1v;
            v1.x = S * ((float)P[mt][nt][2] + (float)Q[mt][nt][2] * (1.f / 254.f)) + b0v;
            v1.y = S * ((float)P[mt][nt][3] + (float)Q[mt][nt][3] * (1.f / 254.f)) + b1v;
            if (mode == 1) {
                float2 c0 = *(const float2*)&cema[r0 * ldc + col];
                float2 c1 = *(const float2*)&cema[(r0 + 8) * ldc + col];
                v0.x = fmaf(w0, v0.x, w1 * c0.x);  v0.y = fmaf(w0, v0.y, w1 * c0.y);
                v1.x = fmaf(w0, v1.x, w1 * c1.x);  v1.y = fmaf(w0, v1.y, w1 * c1.y);
            }
            *(float2*)&C[r0 * ldc + col]       = v0;
            *(float2*)&C[(r0 + 8) * ldc + col] = v1;
        }
    }
}

// ---------------- per-head V column sums ----------------
__global__ void sv_kernel()
{
    const int c  = threadIdx.x;
    const int t0 = blockIdx.x * 128;
    float s = 0.f;
#pragma unroll 4
    for (int t = t0; t < t0 + 128; t++)
        s += g_qkv[t * QKV_LD + 2 * E_DIM + c];
    atomicAdd(&g_sv[c], s);
}

// ---------------- fused block-local attention (fp32 out) ----------------
#define ATTN_SMEM_FLOATS (16384 + 8192 + 128)

__global__ void __launch_bounds__(256)
attn_kernel()
{
    extern __shared__ float sm[];
    float* qv     = sm;
    float* ks     = sm + 8192;
    float* Est    = sm;
    float* vv     = sm + 16384;
    float* rowinv = sm + 16384 + 8192;

    const int tid = threadIdx.x;
    const int h   = blockIdx.x >> 5;
    const int blk = blockIdx.x & 31;
    const int t0  = blk * WSZ;
    const int coff = h * DK;

    for (int idx = tid; idx < 2048; idx += 256) {
        const int i = idx >> 4, d4 = (idx & 15) << 2;
        const float* src = &g_qkv[(t0 + i) * QKV_LD + coff + d4];
        float4 q4 = *(const float4*)src;
        float4 k4 = *(const float4*)(src + E_DIM);
        float4 v4 = *(const float4*)(src + 2 * E_DIM);
        qv[(d4 + 0) * 128 + i] = q4.x;  ks[(d4 + 0) * 128 + i] = k4.x;
        qv[(d4 + 1) * 128 + i] = q4.y;  ks[(d4 + 1) * 128 + i] = k4.y;
        qv[(d4 + 2) * 128 + i] = q4.z;  ks[(d4 + 2) * 128 + i] = k4.z;
        qv[(d4 + 3) * 128 + i] = q4.w;  ks[(d4 + 3) * 128 + i] = k4.w;
        *(float4*)&vv[i * 64 + d4] = v4;
    }
    __syncthreads();

    const int tx = tid & 15, ty = tid >> 4;
    const int ib = tx * 8, jb = ty * 8;
    float accS[8][8];
#pragma unroll
    for (int r = 0; r < 8; r++)
#pragma unroll
        for (int c = 0; c < 8; c++) accS[r][c] = 0.f;

#pragma unroll 4
    for (int d = 0; d < 64; d++) {
        float qr[8], kr[8];
        *(float4*)&qr[0] = *(const float4*)&qv[d * 128 + ib];
        *(float4*)&qr[4] = *(const float4*)&qv[d * 128 + ib + 4];
        *(float4*)&kr[0] = *(const float4*)&ks[d * 128 + jb];
        *(float4*)&kr[4] = *(const float4*)&ks[d * 128 + jb + 4];
#pragma unroll
        for (int r = 0; r < 8; r++)
#pragma unroll
            for (int c = 0; c < 8; c++)
                accS[r][c] = fmaf(qr[r], kr[c], accS[r][c]);
    }
    __syncthreads();

#pragma unroll
    for (int c = 0; c < 8; c++) {
        const int j = jb + c;
        float e[8];
#pragma unroll
        for (int r = 0; r < 8; r++) {
            const int i = ib + r;
            e[r] = (j <= i) ? (expf(accS[r][c] * 0.125f) - 1.0f) : 0.0f;
        }
        *(float4*)&Est[j * 128 + ib]     = make_float4(e[0], e[1], e[2], e[3]);
        *(float4*)&Est[j * 128 + ib + 4] = make_float4(e[4], e[5], e[6], e[7]);
    }
    __syncthreads();

    if (tid < 128) {
        float s = 0.f;
#pragma unroll 4
        for (int j = 0; j < 128; j++) s += Est[j * 128 + tid];
        rowinv[tid] = 1.0f / (s + 4096.0f);
    }
    __syncthreads();

    const int i0 = ty * 8, d0 = tx * 4;
    float accO[8][4];
#pragma unroll
    for (int r = 0; r < 8; r++)
#pragma unroll
        for (int c = 0; c < 4; c++) accO[r][c] = 0.f;

#pragma unroll 2
    for (int j = 0; j < 128; j++) {
        float er[8];
        *(float4*)&er[0] = *(const float4*)&Est[j * 128 + i0];
        *(float4*)&er[4] = *(const float4*)&Est[j * 128 + i0 + 4];
        float4 v4 = *(const float4*)&vv[j * 64 + d0];
#pragma unroll
        for (int r = 0; r < 8; r++) {
            accO[r][0] = fmaf(er[r], v4.x, accO[r][0]);
            accO[r][1] = fmaf(er[r], v4.y, accO[r][1]);
            accO[r][2] = fmaf(er[r], v4.z, accO[r][2]);
            accO[r][3] = fmaf(er[r], v4.w, accO[r][3]);
        }
    }

    const float4 sv4 = *(const float4*)&g_sv[coff + d0];
#pragma unroll
    for (int r = 0; r < 8; r++) {
        const int i = i0 + r;
        const float riv = rowinv[i];
        float4 o;
        o.x = (accO[r][0] + sv4.x) * riv;
        o.y = (accO[r][1] + sv4.y) * riv;
        o.z = (accO[r][2] + sv4.z) * riv;
        o.w = (accO[r][3] + sv4.w) * riv;
        *(float4*)&g_attn[(t0 + i) * E_DIM + coff + d0] = o;
    }
}

// ---------------- CEMA: chunked linear scan ----------------
__global__ void __launch_bounds__(128)
cema_pass1(const float* __restrict__ x, const float* __restrict__ p_coeff,
           const float* __restrict__ q_coeff, const float* __restrict__ gamma)
{
    const int gid  = blockIdx.x * 128 + threadIdx.x;
    const int e    = gid & 511;
    const int chnk = gid >> 9;
    float p[NDIMS], q[NDIMS], g[NDIMS], h[NDIMS];
#pragma unroll
    for (int d = 0; d < NDIMS; d++) {
        p[d] = p_coeff[e * NDIMS + d];
        q[d] = q_coeff[e * NDIMS + d];
        g[d] = gamma  [e * NDIMS + d];
        h[d] = 0.f;
    }
    const int tbase = chnk * CLEN;
    for (int t = 0; t < CLEN; t++) {
        const float xv = x[(tbase + t) * E_DIM + e];
        float y = 0.f;
#pragma unroll
        for (int d = 0; d < NDIMS; d++) {
            h[d] = fmaf(q[d], h[d], p[d] * xv);
            y    = fmaf(g[d], h[d], y);
        }
        g_cema[(tbase + t) * E_DIM + e] = y;
    }
#pragma unroll
    for (int d = 0; d < NDIMS; d++)
        g_hend[chnk * (E_DIM * NDIMS) + e * NDIMS + d] = h[d];
}

__global__ void __launch_bounds__(128)
cema_carry(const float* __restrict__ q_coeff)
{
    const int gid = blockIdx.x * 128 + threadIdx.x;
    const float q = q_coeff[gid];
    float qc = q;
#pragma unroll
    for (int i = 0; i < 6; i++) qc *= qc;              // q^64
    float G = 0.f;
    for (int c = 0; c < CHUNKS; c++) {
        g_carry[c * (E_DIM * NDIMS) + gid] = G;
        G = fmaf(qc, G, g_hend[c * (E_DIM * NDIMS) + gid]);
    }
}

__global__ void __launch_bounds__(128)
cema_pass2(const float* __restrict__ q_coeff, const float* __restrict__ gamma)
{
    const int gid  = blockIdx.x * 128 + threadIdx.x;
    const int e    = gid & 511;
    const int chnk = gid >> 9;
    if (chnk == 0) return;
    float q[NDIMS], w[NDIMS];
#pragma unroll
    for (int d = 0; d < NDIMS; d++) {
        q[d] = q_coeff[e * NDIMS + d];
        w[d] = gamma[e * NDIMS + d] * g_carry[chnk * (E_DIM * NDIMS) + e * NDIMS + d];
    }
    const int tbase = chnk * CLEN;
    for (int t = 0; t < CLEN; t++) {
        float y = 0.f;
#pragma unroll
        for (int d = 0; d < NDIMS; d++) {
            w[d] *= q[d];
            y    += w[d];
        }
        g_cema[(tbase + t) * E_DIM + e] += y;
    }
}

// ---------------------------- launch ----------------------------
extern "C" void kernel_launch(void* const* d_in, const int* in_sizes, int n_in,
                              void* d_out, int out_size)
{
    (void)in_sizes; (void)n_in; (void)out_size;
    const float* x       = (const float*)d_in[0];
    const float* W_qkv   = (const float*)d_in[1];
    const float* b_qkv   = (const float*)d_in[2];
    const float* W_out   = (const float*)d_in[3];
    const float* b_out   = (const float*)d_in[4];
    const float* p_coeff = (const float*)d_in[6];
    const float* q_coeff = (const float*)d_in[7];
    const float* gamma   = (const float*)d_in[8];
    const float* aw      = (const float*)d_in[9];
    float* out = (float*)d_out;

    float *qkvp, *attnp, *cemap, *svp, *amx;
    int8_t *x1, *x2, *a1, *a2, *wq1, *wq2, *wo1, *wo2;
    cudaGetSymbolAddress((void**)&qkvp,  g_qkv);
    cudaGetSymbolAddress((void**)&attnp, g_attn);
    cudaGetSymbolAddress((void**)&cemap, g_cema);
    cudaGetSymbolAddress((void**)&svp,   g_sv);
    cudaGetSymbolAddress((void**)&amx,   g_absmax);
    cudaGetSymbolAddress((void**)&x1,  g_x1);
    cudaGetSymbolAddress((void**)&x2,  g_x2);
    cudaGetSymbolAddress((void**)&a1,  g_a1);
    cudaGetSymbolAddress((void**)&a2,  g_a2);
    cudaGetSymbolAddress((void**)&wq1, g_wq1);
    cudaGetSymbolAddress((void**)&wq2, g_wq2);
    cudaGetSymbolAddress((void**)&wo1, g_wo1);
    cudaGetSymbolAddress((void**)&wo2, g_wo2);

    cudaFuncSetAttribute(gemm_imma, cudaFuncAttributeMaxDynamicSharedMemorySize, GEMM_SMEM_BYTES);
    cudaFuncSetAttribute(attn_kernel, cudaFuncAttributeMaxDynamicSharedMemorySize,
                         ATTN_SMEM_FLOATS * (int)sizeof(float));

    cudaMemsetAsync(svp, 0, E_DIM * sizeof(float));
    cudaMemsetAsync(amx, 0, 4 * sizeof(float));

    // absmax of x, W_qkv, W_out
    absmax_kernel<<<512, 256>>>((const float4*)x, N_TOK * E_DIM / 4, amx + 0);
    absmax_kernel<<<512, 256>>>((const float4*)W_qkv, E_DIM * QKV_LD / 4, amx + 1);
    absmax_kernel<<<256, 256>>>((const float4*)W_out, E_DIM * E_DIM / 4, amx + 2);

    // quantize x and weights (weights transposed to [N x K])
    conv_q8<<<(N_TOK * E_DIM / 4) / 256, 256>>>((const float4*)x, amx + 0, x1, x2);
    transpose_conv_q8<<<dim3(QKV_LD / 32, E_DIM / 32), dim3(32, 8)>>>(W_qkv, amx + 1, wq1, wq2, E_DIM, QKV_LD);
    transpose_conv_q8<<<dim3(E_DIM / 32, E_DIM / 32), dim3(32, 8)>>>(W_out, amx + 2, wo1, wo2, E_DIM, E_DIM);

    // QKV projection (int8 two-level IMMA)
    gemm_imma<<<dim3(QKV_LD / 128, N_TOK / 64), 256, GEMM_SMEM_BYTES>>>(
        x1, x2, wq1, wq2, amx + 0, amx + 1, b_qkv, qkvp, QKV_LD, 0, nullptr, nullptr);

    // per-head V sums
    sv_kernel<<<NBLK, E_DIM>>>();

    // block-local attention (fp32 output)
    attn_kernel<<<NH * NBLK, 256, ATTN_SMEM_FLOATS * (int)sizeof(float)>>>();

    // quantize attention output with its own dynamic scale
    absmax_kernel<<<512, 256>>>((const float4*)attnp, N_TOK * E_DIM / 4, amx + 3);
    conv_q8<<<(N_TOK * E_DIM / 4) / 256, 256>>>((const float4*)attnp, amx + 3, a1, a2);

    // CEMA
    cema_pass1<<<(E_DIM * CHUNKS) / 128, 128>>>(x, p_coeff, q_coeff, gamma);
    cema_carry<<<(E_DIM * NDIMS) / 128, 128>>>(q_coeff);
    cema_pass2<<<(E_DIM * CHUNKS) / 128, 128>>>(q_coeff, gamma);

    // out projection fused with adaptive combine (int8 IMMA)
    gemm_imma<<<dim3(E_DIM / 128, N_TOK / 64), 256, GEMM_SMEM_BYTES>>>(
        a1, a2, wo1, wo2, amx + 3, amx + 2, b_out, out, E_DIM, 1, cemap, aw);
}

// round 8
// speedup vs baseline: 1.6114x; 1.6114x over previous
#include <cuda_runtime.h>
#include <cuda_fp16.h>
#include <cmath>
#include <cstdint>

#define N_TOK 4096
#define E_DIM 512
#define NH 8
#define DK 64
#define WSZ 128
#define NBLK 32
#define NDIMS 16
#define QKV_LD 1536
#define CHUNKS 64
#define CLEN 64
#define KDIM 512
#define LO_SCALE 2048.0f
#define INV_LO (1.0f / 2048.0f)

// ---------------- scratch (device globals) ----------------
__device__ float g_qkv [N_TOK * QKV_LD];
__device__ float g_cema[N_TOK * E_DIM];
__device__ float g_hend [CHUNKS * E_DIM * NDIMS];
__device__ float g_carry[CHUNKS * E_DIM * NDIMS];
__device__ float g_sv[E_DIM];
__device__ __half g_xhi [N_TOK * E_DIM];
__device__ __half g_xlo [N_TOK * E_DIM];
__device__ __half g_ahi [N_TOK * E_DIM];
__device__ __half g_alo [N_TOK * E_DIM];
__device__ __half g_wqT_hi[QKV_LD * E_DIM];
__device__ __half g_wqT_lo[QKV_LD * E_DIM];
__device__ __half g_woT_hi[E_DIM * E_DIM];
__device__ __half g_woT_lo[E_DIM * E_DIM];

// ---------------- PTX helpers ----------------
__device__ __forceinline__ uint32_t smem_u32(const void* p) {
    uint32_t a;
    asm("{ .reg .u64 t; cvta.to.shared.u64 t, %1; cvt.u32.u64 %0, t; }" : "=r"(a) : "l"(p));
    return a;
}
__device__ __forceinline__ void ldsm_x4(uint32_t* r, uint32_t addr) {
    asm volatile("ldmatrix.sync.aligned.m8n8.x4.shared.b16 {%0,%1,%2,%3}, [%4];"
        : "=r"(r[0]), "=r"(r[1]), "=r"(r[2]), "=r"(r[3]) : "r"(addr));
}
__device__ __forceinline__ void ldsm_x2(uint32_t* r, uint32_t addr) {
    asm volatile("ldmatrix.sync.aligned.m8n8.x2.shared.b16 {%0,%1}, [%2];"
        : "=r"(r[0]), "=r"(r[1]) : "r"(addr));
}
// fp16 inputs, fp32 accumulators
__device__ __forceinline__ void mma_f32acc(float* d, const uint32_t* a, const uint32_t* b) {
    asm volatile("mma.sync.aligned.m16n8k16.row.col.f32.f16.f16.f32 "
        "{%0,%1,%2,%3}, {%4,%5,%6,%7}, {%8,%9}, {%0,%1,%2,%3};"
        : "+f"(d[0]), "+f"(d[1]), "+f"(d[2]), "+f"(d[3])
        : "r"(a[0]), "r"(a[1]), "r"(a[2]), "r"(a[3]), "r"(b[0]), "r"(b[1]));
}
// fp16 inputs, fp16 accumulators (2 b32 regs = 4 halves)
__device__ __forceinline__ void mma_f16acc(uint32_t* d, const uint32_t* a, const uint32_t* b) {
    asm volatile("mma.sync.aligned.m16n8k16.row.col.f16.f16.f16.f16 "
        "{%0,%1}, {%2,%3,%4,%5}, {%6,%7}, {%0,%1};"
        : "+r"(d[0]), "+r"(d[1])
        : "r"(a[0]), "r"(a[1]), "r"(a[2]), "r"(a[3]), "r"(b[0]), "r"(b[1]));
}
#define CP_ASYNC16(dst, src) \
    asm volatile("cp.async.cg.shared.global [%0], [%1], 16;" :: "r"(dst), "l"(src))
#define CP_COMMIT()  asm volatile("cp.async.commit_group;" ::: "memory")
#define CP_WAIT_1()  asm volatile("cp.async.wait_group 1;" ::: "memory")
#define CP_WAIT_0()  asm volatile("cp.async.wait_group 0;" ::: "memory")

// ---------------- prep kernels ----------------
__device__ __forceinline__ void split16(float v, __half& h, __half& l) {
    h = __float2half(v);
    l = __float2half((v - __half2float(h)) * LO_SCALE);
}

__global__ void conv_hilo(const float* __restrict__ X,
                          __half* __restrict__ hi, __half* __restrict__ lo)
{
    const int i = blockIdx.x * blockDim.x + threadIdx.x;   // per float4
    float4 v = ((const float4*)X)[i];
    __half hx, lx, hy, ly, hz, lz, hw, lw;
    split16(v.x, hx, lx); split16(v.y, hy, ly);
    split16(v.z, hz, lz); split16(v.w, hw, lw);
    __half2* H = (__half2*)hi;
    __half2* L = (__half2*)lo;
    H[i * 2 + 0] = __half2{hx, hy};  H[i * 2 + 1] = __half2{hz, hw};
    L[i * 2 + 0] = __half2{lx, ly};  L[i * 2 + 1] = __half2{lz, lw};
}

// W [Kdim x Ndim] fp32 -> WT [Ndim x Kdim] fp16 hi/lo
__global__ void transpose_conv(const float* __restrict__ W,
                               __half* __restrict__ Thi, __half* __restrict__ Tlo,
                               int Kdim, int Ndim)
{
    __shared__ float t[32][33];
    const int n0 = blockIdx.x * 32, k0 = blockIdx.y * 32;
    const int tx = threadIdx.x, ty = threadIdx.y;
#pragma unroll
    for (int s = 0; s < 32; s += 8)
        t[ty + s][tx] = W[(k0 + ty + s) * Ndim + n0 + tx];
    __syncthreads();
#pragma unroll
    for (int s = 0; s < 32; s += 8) {
        float v = t[tx][ty + s];
        __half h, l;
        split16(v, h, l);
        Thi[(n0 + ty + s) * Kdim + k0 + tx] = h;
        Tlo[(n0 + ty + s) * Kdim + k0 + tx] = l;
    }
}

// ---------------- fp16x3 tensor-core GEMM (corrections in fp16 accum) ----------------
// CTA 64(M) x 128(N), 128 thr = 4 warps across N, warp tile 64x32.
// D = f32acc(Ah*Bh) + INV_LO * f16acc(Ah*Bl + Al*Bh) + bias
#define KC 32
#define NCH (KDIM / KC)
#define LDSB 80
#define ST_AH 0
#define ST_AL 5120
#define ST_BH 10240
#define ST_BL 20480
#define STAGE_B 30720
#define GEMM_SMEM_BYTES (2 * STAGE_B)

__device__ __forceinline__ void gemm_load_chunk(
    uint32_t stage_sb, const __half* Ahi, const __half* Alo,
    const __half* Bhi, const __half* Blo, int m0, int n0, int kb, int tid)
{
#pragma unroll
    for (int i = 0; i < 2; i++) {                    // A: 64 rows x 4 segs
        const int idx = tid + i * 128;
        const int r = idx >> 2, seg = idx & 3;
        const uint32_t so = stage_sb + (uint32_t)(r * LDSB + seg * 16);
        const long ga = (long)(m0 + r) * KDIM + kb + seg * 8;
        CP_ASYNC16(so + ST_AH, Ahi + ga);
        CP_ASYNC16(so + ST_AL, Alo + ga);
    }
#pragma unroll
    for (int i = 0; i < 4; i++) {                    // B: 128 rows x 4 segs
        const int idx = tid + i * 128;
        const int r = idx >> 2, seg = idx & 3;
        const uint32_t so = stage_sb + (uint32_t)(r * LDSB + seg * 16);
        const long gb = (long)(n0 + r) * KDIM + kb + seg * 8;
        CP_ASYNC16(so + ST_BH, Bhi + gb);
        CP_ASYNC16(so + ST_BL, Blo + gb);
    }
}

__global__ void __launch_bounds__(128, 2)
gemm_mma(const __half* __restrict__ Ahi, const __half* __restrict__ Alo,
         const __half* __restrict__ Bhi, const __half* __restrict__ Blo,
         const float* __restrict__ bias, float* __restrict__ C, int ldc, int mode,
         const float* __restrict__ cema, const float* __restrict__ aw)
{
    extern __shared__ __align__(16) char smem[];
    const uint32_t sb = smem_u32(smem);
    const int tid = threadIdx.x;
    const int wn = tid >> 5, lane = tid & 31;         // 4 warps across N
    const int m0 = blockIdx.y * 64, n0 = blockIdx.x * 128;

    const uint32_t a_off = (uint32_t)(lane & 15) * LDSB + ((lane >> 4) << 4);
    const uint32_t b_off = (uint32_t)(wn * 32 + (lane & 7)) * LDSB + (((lane >> 3) & 1) << 4);

    float acc[4][4][4];
    uint32_t hacc[4][4][2];
#pragma unroll
    for (int mt = 0; mt < 4; mt++)
#pragma unroll
        for (int nt = 0; nt < 4; nt++) {
#pragma unroll
            for (int c = 0; c < 4; c++) acc[mt][nt][c] = 0.f;
            hacc[mt][nt][0] = 0u; hacc[mt][nt][1] = 0u;
        }

    gemm_load_chunk(sb, Ahi, Alo, Bhi, Blo, m0, n0, 0, tid);
    CP_COMMIT();

    for (int ch = 0; ch < NCH; ch++) {
        const uint32_t st = sb + (uint32_t)((ch & 1) * STAGE_B);
        if (ch + 1 < NCH) {
            gemm_load_chunk(sb + (uint32_t)(((ch + 1) & 1) * STAGE_B),
                            Ahi, Alo, Bhi, Blo, m0, n0, (ch + 1) * KC, tid);
            CP_COMMIT();
            CP_WAIT_1();
        } else {
            CP_WAIT_0();
        }
        __syncthreads();

#pragma unroll
        for (int ks = 0; ks < 2; ks++) {
            const uint32_t kofs = ks * 32;
            uint32_t bh2[4][2], bl2[4][2];
#pragma unroll
            for (int nt = 0; nt < 4; nt++) {
                ldsm_x2(bh2[nt], st + ST_BH + b_off + nt * (8 * LDSB) + kofs);
                ldsm_x2(bl2[nt], st + ST_BL + b_off + nt * (8 * LDSB) + kofs);
            }
#pragma unroll
            for (int mt = 0; mt < 4; mt++) {
                uint32_t ah[4], al[4];
                ldsm_x4(ah, st + ST_AH + a_off + mt * (16 * LDSB) + kofs);
                ldsm_x4(al, st + ST_AL + a_off + mt * (16 * LDSB) + kofs);
#pragma unroll
                for (int nt = 0; nt < 4; nt++) {
                    mma_f32acc(acc[mt][nt], ah, bh2[nt]);     // main term
                    mma_f16acc(hacc[mt][nt], ah, bl2[nt]);    // Ah*Bl (x2048)
                    mma_f16acc(hacc[mt][nt], al, bh2[nt]);    // Al*Bh (x2048)
                }
            }
        }
        __syncthreads();
    }

    float w0 = 1.f, w1 = 0.f;
    if (mode == 1) {
        float a0 = aw[0], a1 = aw[1];
        float mx = fmaxf(a0, a1);
        float e0 = expf(a0 - mx), e1 = expf(a1 - mx);
        float inv = 1.f / (e0 + e1);
        w0 = e0 * inv; w1 = e1 * inv;
    }

#pragma unroll
    for (int mt = 0; mt < 4; mt++) {
        const int r0 = m0 + mt * 16 + (lane >> 2);
#pragma unroll
        for (int nt = 0; nt < 4; nt++) {
            const int col = n0 + wn * 32 + nt * 8 + (lane & 3) * 2;
            const float b0v = bias[col], b1v = bias[col + 1];
            float2 q01 = __half22float2(*(const __half2*)&hacc[mt][nt][0]);
            float2 q23 = __half22float2(*(const __half2*)&hacc[mt][nt][1]);
            float2 v0, v1;
            v0.x = acc[mt][nt][0] + q01.x * INV_LO + b0v;
            v0.y = acc[mt][nt][1] + q01.y * INV_LO + b1v;
            v1.x = acc[mt][nt][2] + q23.x * INV_LO + b0v;
            v1.y = acc[mt][nt][3] + q23.y * INV_LO + b1v;
            if (mode == 1) {
                float2 c0 = *(const float2*)&cema[r0 * ldc + col];
                float2 c1 = *(const float2*)&cema[(r0 + 8) * ldc + col];
                v0.x = fmaf(w0, v0.x, w1 * c0.x);  v0.y = fmaf(w0, v0.y, w1 * c0.y);
                v1.x = fmaf(w0, v1.x, w1 * c1.x);  v1.y = fmaf(w0, v1.y, w1 * c1.y);
            }
            *(float2*)&C[r0 * ldc + col]       = v0;
            *(float2*)&C[(r0 + 8) * ldc + col] = v1;
        }
    }
}

// ---------------- per-head V column sums ----------------
__global__ void sv_kernel()
{
    const int c  = threadIdx.x;
    const int t0 = blockIdx.x * 128;
    float s = 0.f;
#pragma unroll 4
    for (int t = t0; t < t0 + 128; t++)
        s += g_qkv[t * QKV_LD + 2 * E_DIM + c];
    atomicAdd(&g_sv[c], s);
}

// ---------------- fused block-local attention ----------------
#define ATTN_SMEM_FLOATS (16384 + 8192 + 128)

__global__ void __launch_bounds__(256)
attn_kernel()
{
    extern __shared__ float sm[];
    float* qv     = sm;
    float* ks     = sm + 8192;
    float* Est    = sm;              // overlaps q/k after S is in registers
    float* vv     = sm + 16384;
    float* rowinv = sm + 16384 + 8192;

    const int tid = threadIdx.x;
    const int h   = blockIdx.x >> 5;
    const int blk = blockIdx.x & 31;
    const int t0  = blk * WSZ;
    const int coff = h * DK;

    for (int idx = tid; idx < 2048; idx += 256) {
        const int i = idx >> 4, d4 = (idx & 15) << 2;
        const float* src = &g_qkv[(t0 + i) * QKV_LD + coff + d4];
        float4 q4 = *(const float4*)src;
        float4 k4 = *(const float4*)(src + E_DIM);
        float4 v4 = *(const float4*)(src + 2 * E_DIM);
        qv[(d4 + 0) * 128 + i] = q4.x;  ks[(d4 + 0) * 128 + i] = k4.x;
        qv[(d4 + 1) * 128 + i] = q4.y;  ks[(d4 + 1) * 128 + i] = k4.y;
        qv[(d4 + 2) * 128 + i] = q4.z;  ks[(d4 + 2) * 128 + i] = k4.z;
        qv[(d4 + 3) * 128 + i] = q4.w;  ks[(d4 + 3) * 128 + i] = k4.w;
        *(float4*)&vv[i * 64 + d4] = v4;
    }
    __syncthreads();

    const int tx = tid & 15, ty = tid >> 4;
    const int ib = tx * 8, jb = ty * 8;
    float accS[8][8];
#pragma unroll
    for (int r = 0; r < 8; r++)
#pragma unroll
        for (int c = 0; c < 8; c++) accS[r][c] = 0.f;

#pragma unroll 4
    for (int d = 0; d < 64; d++) {
        float qr[8], kr[8];
        *(float4*)&qr[0] = *(const float4*)&qv[d * 128 + ib];
        *(float4*)&qr[4] = *(const float4*)&qv[d * 128 + ib + 4];
        *(float4*)&kr[0] = *(const float4*)&ks[d * 128 + jb];
        *(float4*)&kr[4] = *(const float4*)&ks[d * 128 + jb + 4];
#pragma unroll
        for (int r = 0; r < 8; r++)
#pragma unroll
            for (int c = 0; c < 8; c++)
                accS[r][c] = fmaf(qr[r], kr[c], accS[r][c]);
    }
    __syncthreads();

#pragma unroll
    for (int c = 0; c < 8; c++) {
        const int j = jb + c;
        float e[8];
#pragma unroll
        for (int r = 0; r < 8; r++) {
            const int i = ib + r;
            e[r] = (j <= i) ? (expf(accS[r][c] * 0.125f) - 1.0f) : 0.0f;
        }
        *(float4*)&Est[j * 128 + ib]     = make_float4(e[0], e[1], e[2], e[3]);
        *(float4*)&Est[j * 128 + ib + 4] = make_float4(e[4], e[5], e[6], e[7]);
    }
    __syncthreads();

    if (tid < 128) {
        float s = 0.f;
#pragma unroll 4
        for (int j = 0; j < 128; j++) s += Est[j * 128 + tid];
        rowinv[tid] = 1.0f / (s + 4096.0f);
    }
    __syncthreads();

    const int i0 = ty * 8, d0 = tx * 4;
    float accO[8][4];
#pragma unroll
    for (int r = 0; r < 8; r++)
#pragma unroll
        for (int c = 0; c < 4; c++) accO[r][c] = 0.f;

#pragma unroll 2
    for (int j = 0; j < 128; j++) {
        float er[8];
        *(float4*)&er[0] = *(const float4*)&Est[j * 128 + i0];
        *(float4*)&er[4] = *(const float4*)&Est[j * 128 + i0 + 4];
        float4 v4 = *(const float4*)&vv[j * 64 + d0];
#pragma unroll
        for (int r = 0; r < 8; r++) {
            accO[r][0] = fmaf(er[r], v4.x, accO[r][0]);
            accO[r][1] = fmaf(er[r], v4.y, accO[r][1]);
            accO[r][2] = fmaf(er[r], v4.z, accO[r][2]);
            accO[r][3] = fmaf(er[r], v4.w, accO[r][3]);
        }
    }

    const float4 sv4 = *(const float4*)&g_sv[coff + d0];
#pragma unroll
    for (int r = 0; r < 8; r++) {
        const int i = i0 + r;
        const float riv = rowinv[i];
        float4 o;
        o.x = (accO[r][0] + sv4.x) * riv;
        o.y = (accO[r][1] + sv4.y) * riv;
        o.z = (accO[r][2] + sv4.z) * riv;
        o.w = (accO[r][3] + sv4.w) * riv;
        __half hx, lx, hy, ly, hz, lz, hw, lw;
        split16(o.x, hx, lx); split16(o.y, hy, ly);
        split16(o.z, hz, lz); split16(o.w, hw, lw);
        const int base = ((t0 + i) * E_DIM + coff + d0) >> 1;
        __half2* H = (__half2*)g_ahi;
        __half2* L = (__half2*)g_alo;
        H[base + 0] = __half2{hx, hy};  H[base + 1] = __half2{hz, hw};
        L[base + 0] = __half2{lx, ly};  L[base + 1] = __half2{lz, lw};
    }
}

// ---------------- CEMA: chunked linear scan ----------------
__global__ void __launch_bounds__(128)
cema_pass1(const float* __restrict__ x, const float* __restrict__ p_coeff,
           const float* __restrict__ q_coeff, const float* __restrict__ gamma)
{
    const int gid  = blockIdx.x * 128 + threadIdx.x;
    const int e    = gid & 511;
    const int chnk = gid >> 9;
    float p[NDIMS], q[NDIMS], g[NDIMS], h[NDIMS];
#pragma unroll
    for (int d = 0; d < NDIMS; d++) {
        p[d] = p_coeff[e * NDIMS + d];
        q[d] = q_coeff[e * NDIMS + d];
        g[d] = gamma  [e * NDIMS + d];
        h[d] = 0.f;
    }
    const int tbase = chnk * CLEN;
    for (int t = 0; t < CLEN; t++) {
        const float xv = x[(tbase + t) * E_DIM + e];
        float y = 0.f;
#pragma unroll
        for (int d = 0; d < NDIMS; d++) {
            h[d] = fmaf(q[d], h[d], p[d] * xv);
            y    = fmaf(g[d], h[d], y);
        }
        g_cema[(tbase + t) * E_DIM + e] = y;
    }
#pragma unroll
    for (int d = 0; d < NDIMS; d++)
        g_hend[chnk * (E_DIM * NDIMS) + e * NDIMS + d] = h[d];
}

__global__ void __launch_bounds__(128)
cema_carry(const float* __restrict__ q_coeff)
{
    const int gid = blockIdx.x * 128 + threadIdx.x;
    const float q = q_coeff[gid];
    float qc = q;
#pragma unroll
    for (int i = 0; i < 6; i++) qc *= qc;              // q^64
    float G = 0.f;
    for (int c = 0; c < CHUNKS; c++) {
        g_carry[c * (E_DIM * NDIMS) + gid] = G;
        G = fmaf(qc, G, g_hend[c * (E_DIM * NDIMS) + gid]);
    }
}

__global__ void __launch_bounds__(128)
cema_pass2(const float* __restrict__ q_coeff, const float* __restrict__ gamma)
{
    const int gid  = blockIdx.x * 128 + threadIdx.x;
    const int e    = gid & 511;
    const int chnk = gid >> 9;
    if (chnk == 0) return;
    float q[NDIMS], w[NDIMS];
#pragma unroll
    for (int d = 0; d < NDIMS; d++) {
        q[d] = q_coeff[e * NDIMS + d];
        w[d] = gamma[e * NDIMS + d] * g_carry[chnk * (E_DIM * NDIMS) + e * NDIMS + d];
    }
    const int tbase = chnk * CLEN;
    for (int t = 0; t < CLEN; t++) {
        float y = 0.f;
#pragma unroll
        for (int d = 0; d < NDIMS; d++) {
            w[d] *= q[d];
            y    += w[d];
        }
        g_cema[(tbase + t) * E_DIM + e] += y;
    }
}

// ---------------------------- launch ----------------------------
extern "C" void kernel_launch(void* const* d_in, const int* in_sizes, int n_in,
                              void* d_out, int out_size)
{
    (void)in_sizes; (void)n_in; (void)out_size;
    const float* x       = (const float*)d_in[0];
    const float* W_qkv   = (const float*)d_in[1];
    const float* b_qkv   = (const float*)d_in[2];
    const float* W_out   = (const float*)d_in[3];
    const float* b_out   = (const float*)d_in[4];
    const float* p_coeff = (const float*)d_in[6];
    const float* q_coeff = (const float*)d_in[7];
    const float* gamma   = (const float*)d_in[8];
    const float* aw      = (const float*)d_in[9];
    float* out = (float*)d_out;

    float *qkvp, *cemap, *svp;
    __half *xhi, *xlo, *ahi, *alo, *wqh, *wql, *woh, *wol;
    cudaGetSymbolAddress((void**)&qkvp,  g_qkv);
    cudaGetSymbolAddress((void**)&cemap, g_cema);
    cudaGetSymbolAddress((void**)&svp,   g_sv);
    cudaGetSymbolAddress((void**)&xhi, g_xhi);
    cudaGetSymbolAddress((void**)&xlo, g_xlo);
    cudaGetSymbolAddress((void**)&ahi, g_ahi);
    cudaGetSymbolAddress((void**)&alo, g_alo);
    cudaGetSymbolAddress((void**)&wqh, g_wqT_hi);
    cudaGetSymbolAddress((void**)&wql, g_wqT_lo);
    cudaGetSymbolAddress((void**)&woh, g_woT_hi);
    cudaGetSymbolAddress((void**)&wol, g_woT_lo);

    cudaFuncSetAttribute(gemm_mma, cudaFuncAttributeMaxDynamicSharedMemorySize, GEMM_SMEM_BYTES);
    cudaFuncSetAttribute(attn_kernel, cudaFuncAttributeMaxDynamicSharedMemorySize,
                         ATTN_SMEM_FLOATS * (int)sizeof(float));

    cudaMemsetAsync(svp, 0, E_DIM * sizeof(float));
    conv_hilo<<<(N_TOK * E_DIM / 4) / 256, 256>>>(x, xhi, xlo);
    transpose_conv<<<dim3(QKV_LD / 32, E_DIM / 32), dim3(32, 8)>>>(W_qkv, wqh, wql, E_DIM, QKV_LD);
    transpose_conv<<<dim3(E_DIM / 32, E_DIM / 32), dim3(32, 8)>>>(W_out, woh, wol, E_DIM, E_DIM);

    // QKV projection: 64x128 tiles -> grid (12, 64)
    gemm_mma<<<dim3(QKV_LD / 128, N_TOK / 64), 128, GEMM_SMEM_BYTES>>>(
        xhi, xlo, wqh, wql, b_qkv, qkvp, QKV_LD, 0, nullptr, nullptr);

    // per-head V sums
    sv_kernel<<<NBLK, E_DIM>>>();

    // block-local attention (writes fp16 hi/lo)
    attn_kernel<<<NH * NBLK, 256, ATTN_SMEM_FLOATS * (int)sizeof(float)>>>();

    // CEMA
    cema_pass1<<<(E_DIM * CHUNKS) / 128, 128>>>(x, p_coeff, q_coeff, gamma);
    cema_carry<<<(E_DIM * NDIMS) / 128, 128>>>(q_coeff);
    cema_pass2<<<(E_DIM * CHUNKS) / 128, 128>>>(q_coeff, gamma);

    // out projection fused with adaptive combine
    gemm_mma<<<dim3(E_DIM / 128, N_TOK / 64), 128, GEMM_SMEM_BYTES>>>(
        ahi, alo, woh, wol, b_out, out, E_DIM, 1, cemap, aw);
}

// round 9
// speedup vs baseline: 2.0131x; 1.2493x over previous
#include <cuda_runtime.h>
#include <cuda_bf16.h>
#include <cmath>
#include <cstdint>

#define N_TOK 4096
#define E_DIM 512
#define NH 8
#define DK 64
#define WSZ 128
#define NBLK 32
#define NDIMS 16
#define QKV_LD 1536
#define CHUNKS 64
#define CLEN 64
#define KDIM 512

// ---------------- scratch (device globals) ----------------
__device__ float g_qkv [N_TOK * QKV_LD];
__device__ float g_cema[N_TOK * E_DIM];
__device__ float g_hend [CHUNKS * E_DIM * NDIMS];
__device__ float g_carry[CHUNKS * E_DIM * NDIMS];
__device__ float g_sv[E_DIM];
__device__ __nv_bfloat16 g_xhi [N_TOK * E_DIM];
__device__ __nv_bfloat16 g_xlo [N_TOK * E_DIM];
__device__ __nv_bfloat16 g_ahi [N_TOK * E_DIM];
__device__ __nv_bfloat16 g_alo [N_TOK * E_DIM];
__device__ __nv_bfloat16 g_wqT_hi[QKV_LD * E_DIM];
__device__ __nv_bfloat16 g_wqT_lo[QKV_LD * E_DIM];
__device__ __nv_bfloat16 g_woT_hi[E_DIM * E_DIM];
__device__ __nv_bfloat16 g_woT_lo[E_DIM * E_DIM];

// ---------------- PTX helpers ----------------
__device__ __forceinline__ uint32_t smem_u32(const void* p) {
    uint32_t a;
    asm("{ .reg .u64 t; cvta.to.shared.u64 t, %1; cvt.u32.u64 %0, t; }" : "=r"(a) : "l"(p));
    return a;
}
__device__ __forceinline__ void ldsm_x4(uint32_t* r, uint32_t addr) {
    asm volatile("ldmatrix.sync.aligned.m8n8.x4.shared.b16 {%0,%1,%2,%3}, [%4];"
        : "=r"(r[0]), "=r"(r[1]), "=r"(r[2]), "=r"(r[3]) : "r"(addr));
}
__device__ __forceinline__ void ldsm_x2(uint32_t* r, uint32_t addr) {
    asm volatile("ldmatrix.sync.aligned.m8n8.x2.shared.b16 {%0,%1}, [%2];"
        : "=r"(r[0]), "=r"(r[1]) : "r"(addr));
}
__device__ __forceinline__ void mma_bf16(float* d, const uint32_t* a, const uint32_t* b) {
    asm volatile("mma.sync.aligned.m16n8k16.row.col.f32.bf16.bf16.f32 "
        "{%0,%1,%2,%3}, {%4,%5,%6,%7}, {%8,%9}, {%0,%1,%2,%3};"
        : "+f"(d[0]), "+f"(d[1]), "+f"(d[2]), "+f"(d[3])
        : "r"(a[0]), "r"(a[1]), "r"(a[2]), "r"(a[3]), "r"(b[0]), "r"(b[1]));
}
#define CP_ASYNC16(dst, src) \
    asm volatile("cp.async.cg.shared.global [%0], [%1], 16;" :: "r"(dst), "l"(src))
#define CP_COMMIT()  asm volatile("cp.async.commit_group;" ::: "memory")
#define CP_WAIT_1()  asm volatile("cp.async.wait_group 1;" ::: "memory")
#define CP_WAIT_0()  asm volatile("cp.async.wait_group 0;" ::: "memory")

// ---------------- prep kernels ----------------
__global__ void conv_hilo(const float* __restrict__ X,
                          __nv_bfloat16* __restrict__ hi, __nv_bfloat16* __restrict__ lo)
{
    const int i = blockIdx.x * blockDim.x + threadIdx.x;   // per float4
    float4 v = ((const float4*)X)[i];
    __nv_bfloat16 hx = __float2bfloat16(v.x), hy = __float2bfloat16(v.y);
    __nv_bfloat16 hz = __float2bfloat16(v.z), hw = __float2bfloat16(v.w);
    __nv_bfloat162* H = (__nv_bfloat162*)hi;
    __nv_bfloat162* L = (__nv_bfloat162*)lo;
    H[i * 2 + 0] = __nv_bfloat162{hx, hy};
    H[i * 2 + 1] = __nv_bfloat162{hz, hw};
    L[i * 2 + 0] = __nv_bfloat162{__float2bfloat16(v.x - __bfloat162float(hx)),
                                  __float2bfloat16(v.y - __bfloat162float(hy))};
    L[i * 2 + 1] = __nv_bfloat162{__float2bfloat16(v.z - __bfloat162float(hz)),
                                  __float2bfloat16(v.w - __bfloat162float(hw))};
}

// W [Kdim x Ndim] fp32 -> WT [Ndim x Kdim] bf16 hi/lo
__global__ void transpose_conv(const float* __restrict__ W,
                               __nv_bfloat16* __restrict__ Thi, __nv_bfloat16* __restrict__ Tlo,
                               int Kdim, int Ndim)
{
    __shared__ float t[32][33];
    const int n0 = blockIdx.x * 32, k0 = blockIdx.y * 32;
    const int tx = threadIdx.x, ty = threadIdx.y;
#pragma unroll
    for (int s = 0; s < 32; s += 8)
        t[ty + s][tx] = W[(k0 + ty + s) * Ndim + n0 + tx];
    __syncthreads();
#pragma unroll
    for (int s = 0; s < 32; s += 8) {
        float v = t[tx][ty + s];
        __nv_bfloat16 h = __float2bfloat16(v);
        Thi[(n0 + ty + s) * Kdim + k0 + tx] = h;
        Tlo[(n0 + ty + s) * Kdim + k0 + tx] = __float2bfloat16(v - __bfloat162float(h));
    }
}

// ---------------- bf16x3 tensor-core GEMM (R5 best config) ----------------
// CTA 64(M) x 128(N), 128 thr = 4 warps across N, warp 64x32, KC=32, 2-stage cp.async.
#define KC 32
#define NCH (KDIM / KC)
#define LDSB 80
#define ST_AH 0
#define ST_AL 5120
#define ST_BH 10240
#define ST_BL 20480
#define STAGE_B 30720
#define GEMM_SMEM_BYTES (2 * STAGE_B)

__device__ __forceinline__ void gemm_load_chunk(
    uint32_t stage_sb, const __nv_bfloat16* Ahi, const __nv_bfloat16* Alo,
    const __nv_bfloat16* Bhi, const __nv_bfloat16* Blo,
    int m0, int n0, int kb, int tid)
{
#pragma unroll
    for (int i = 0; i < 2; i++) {                    // A: 64 rows x 4 segs
        const int idx = tid + i * 128;
        const int r = idx >> 2, seg = idx & 3;
        const uint32_t so = stage_sb + (uint32_t)(r * LDSB + seg * 16);
        const long ga = (long)(m0 + r) * KDIM + kb + seg * 8;
        CP_ASYNC16(so + ST_AH, Ahi + ga);
        CP_ASYNC16(so + ST_AL, Alo + ga);
    }
#pragma unroll
    for (int i = 0; i < 4; i++) {                    // B: 128 rows x 4 segs
        const int idx = tid + i * 128;
        const int r = idx >> 2, seg = idx & 3;
        const uint32_t so = stage_sb + (uint32_t)(r * LDSB + seg * 16);
        const long gb = (long)(n0 + r) * KDIM + kb + seg * 8;
        CP_ASYNC16(so + ST_BH, Bhi + gb);
        CP_ASYNC16(so + ST_BL, Blo + gb);
    }
}

__global__ void __launch_bounds__(128, 3)
gemm_mma(const __nv_bfloat16* __restrict__ Ahi, const __nv_bfloat16* __restrict__ Alo,
         const __nv_bfloat16* __restrict__ Bhi, const __nv_bfloat16* __restrict__ Blo,
         const float* __restrict__ bias, float* __restrict__ C, int ldc, int mode,
         const float* __restrict__ cema, const float* __restrict__ aw)
{
    extern __shared__ __align__(16) char smem[];
    const uint32_t sb = smem_u32(smem);
    const int tid = threadIdx.x;
    const int wn = tid >> 5, lane = tid & 31;
    const int m0 = blockIdx.y * 64, n0 = blockIdx.x * 128;

    const uint32_t a_off = (uint32_t)(lane & 15) * LDSB + ((lane >> 4) << 4);
    const uint32_t b_off = (uint32_t)(wn * 32 + (lane & 7)) * LDSB + (((lane >> 3) & 1) << 4);

    float acc[4][4][4];
#pragma unroll
    for (int mt = 0; mt < 4; mt++)
#pragma unroll
        for (int nt = 0; nt < 4; nt++)
#pragma unroll
            for (int c = 0; c < 4; c++) acc[mt][nt][c] = 0.f;

    gemm_load_chunk(sb, Ahi, Alo, Bhi, Blo, m0, n0, 0, tid);
    CP_COMMIT();

    for (int ch = 0; ch < NCH; ch++) {
        const uint32_t st = sb + (uint32_t)((ch & 1) * STAGE_B);
        if (ch + 1 < NCH) {
            gemm_load_chunk(sb + (uint32_t)(((ch + 1) & 1) * STAGE_B),
                            Ahi, Alo, Bhi, Blo, m0, n0, (ch + 1) * KC, tid);
            CP_COMMIT();
            CP_WAIT_1();
        } else {
            CP_WAIT_0();
        }
        __syncthreads();

#pragma unroll
        for (int ks = 0; ks < 2; ks++) {
            const uint32_t kofs = ks * 32;
            uint32_t bh[4][2], bl[4][2];
#pragma unroll
            for (int nt = 0; nt < 4; nt++) {
                ldsm_x2(bh[nt], st + ST_BH + b_off + nt * (8 * LDSB) + kofs);
                ldsm_x2(bl[nt], st + ST_BL + b_off + nt * (8 * LDSB) + kofs);
            }
#pragma unroll
            for (int mt = 0; mt < 4; mt++) {
                uint32_t ah[4], al[4];
                ldsm_x4(ah, st + ST_AH + a_off + mt * (16 * LDSB) + kofs);
                ldsm_x4(al, st + ST_AL + a_off + mt * (16 * LDSB) + kofs);
#pragma unroll
                for (int nt = 0; nt < 4; nt++) {
                    mma_bf16(acc[mt][nt], ah, bh[nt]);
                    mma_bf16(acc[mt][nt], ah, bl[nt]);
                    mma_bf16(acc[mt][nt], al, bh[nt]);
                }
            }
        }
        __syncthreads();
    }

    float w0 = 1.f, w1 = 0.f;
    if (mode == 1) {
        float a0 = aw[0], a1 = aw[1];
        float mx = fmaxf(a0, a1);
        float e0 = expf(a0 - mx), e1 = expf(a1 - mx);
        float inv = 1.f / (e0 + e1);
        w0 = e0 * inv; w1 = e1 * inv;
    }

#pragma unroll
    for (int mt = 0; mt < 4; mt++) {
        const int r0 = m0 + mt * 16 + (lane >> 2);
#pragma unroll
        for (int nt = 0; nt < 4; nt++) {
            const int col = n0 + wn * 32 + nt * 8 + (lane & 3) * 2;
            const float b0v = bias[col], b1v = bias[col + 1];
            float2 v0 = make_float2(acc[mt][nt][0] + b0v, acc[mt][nt][1] + b1v);
            float2 v1 = make_float2(acc[mt][nt][2] + b0v, acc[mt][nt][3] + b1v);
            if (mode == 1) {
                float2 c0 = *(const float2*)&cema[r0 * ldc + col];
                float2 c1 = *(const float2*)&cema[(r0 + 8) * ldc + col];
                v0.x = fmaf(w0, v0.x, w1 * c0.x);  v0.y = fmaf(w0, v0.y, w1 * c0.y);
                v1.x = fmaf(w0, v1.x, w1 * c1.x);  v1.y = fmaf(w0, v1.y, w1 * c1.y);
            }
            *(float2*)&C[r0 * ldc + col]       = v0;
            *(float2*)&C[(r0 + 8) * ldc + col] = v1;
        }
    }
}

// ---------------- per-head V column sums ----------------
__global__ void sv_kernel()
{
    const int c  = threadIdx.x;
    const int t0 = blockIdx.x * 128;
    float s = 0.f;
#pragma unroll 4
    for (int t = t0; t < t0 + 128; t++)
        s += g_qkv[t * QKV_LD + 2 * E_DIM + c];
    atomicAdd(&g_sv[c], s);
}

// ---------------- fused block-local attention ----------------
#define ATTN_SMEM_FLOATS (16384 + 8192 + 128)

__global__ void __launch_bounds__(256)
attn_kernel()
{
    extern __shared__ float sm[];
    float* qv     = sm;
    float* ks     = sm + 8192;
    float* Est    = sm;
    float* vv     = sm + 16384;
    float* rowinv = sm + 16384 + 8192;

    const int tid = threadIdx.x;
    const int h   = blockIdx.x >> 5;
    const int blk = blockIdx.x & 31;
    const int t0  = blk * WSZ;
    const int coff = h * DK;

    for (int idx = tid; idx < 2048; idx += 256) {
        const int i = idx >> 4, d4 = (idx & 15) << 2;
        const float* src = &g_qkv[(t0 + i) * QKV_LD + coff + d4];
        float4 q4 = *(const float4*)src;
        float4 k4 = *(const float4*)(src + E_DIM);
        float4 v4 = *(const float4*)(src + 2 * E_DIM);
        qv[(d4 + 0) * 128 + i] = q4.x;  ks[(d4 + 0) * 128 + i] = k4.x;
        qv[(d4 + 1) * 128 + i] = q4.y;  ks[(d4 + 1) * 128 + i] = k4.y;
        qv[(d4 + 2) * 128 + i] = q4.z;  ks[(d4 + 2) * 128 + i] = k4.z;
        qv[(d4 + 3) * 128 + i] = q4.w;  ks[(d4 + 3) * 128 + i] = k4.w;
        *(float4*)&vv[i * 64 + d4] = v4;
    }
    __syncthreads();

    const int tx = tid & 15, ty = tid >> 4;
    const int ib = tx * 8, jb = ty * 8;
    float accS[8][8];
#pragma unroll
    for (int r = 0; r < 8; r++)
#pragma unroll
        for (int c = 0; c < 8; c++) accS[r][c] = 0.f;

#pragma unroll 4
    for (int d = 0; d < 64; d++) {
        float qr[8], kr[8];
        *(float4*)&qr[0] = *(const float4*)&qv[d * 128 + ib];
        *(float4*)&qr[4] = *(const float4*)&qv[d * 128 + ib + 4];
        *(float4*)&kr[0] = *(const float4*)&ks[d * 128 + jb];
        *(float4*)&kr[4] = *(const float4*)&ks[d * 128 + jb + 4];
#pragma unroll
        for (int r = 0; r < 8; r++)
#pragma unroll
            for (int c = 0; c < 8; c++)
                accS[r][c] = fmaf(qr[r], kr[c], accS[r][c]);
    }
    __syncthreads();

#pragma unroll
    for (int c = 0; c < 8; c++) {
        const int j = jb + c;
        float e[8];
#pragma unroll
        for (int r = 0; r < 8; r++) {
            const int i = ib + r;
            e[r] = (j <= i) ? (expf(accS[r][c] * 0.125f) - 1.0f) : 0.0f;
        }
        *(float4*)&Est[j * 128 + ib]     = make_float4(e[0], e[1], e[2], e[3]);
        *(float4*)&Est[j * 128 + ib + 4] = make_float4(e[4], e[5], e[6], e[7]);
    }
    __syncthreads();

    if (tid < 128) {
        float s = 0.f;
#pragma unroll 4
        for (int j = 0; j < 128; j++) s += Est[j * 128 + tid];
        rowinv[tid] = 1.0f / (s + 4096.0f);
    }
    __syncthreads();

    const int i0 = ty * 8, d0 = tx * 4;
    float accO[8][4];
#pragma unroll
    for (int r = 0; r < 8; r++)
#pragma unroll
        for (int c = 0; c < 4; c++) accO[r][c] = 0.f;

#pragma unroll 2
    for (int j = 0; j < 128; j++) {
        float er[8];
        *(float4*)&er[0] = *(const float4*)&Est[j * 128 + i0];
        *(float4*)&er[4] = *(const float4*)&Est[j * 128 + i0 + 4];
        float4 v4 = *(const float4*)&vv[j * 64 + d0];
#pragma unroll
        for (int r = 0; r < 8; r++) {
            accO[r][0] = fmaf(er[r], v4.x, accO[r][0]);
            accO[r][1] = fmaf(er[r], v4.y, accO[r][1]);
            accO[r][2] = fmaf(er[r], v4.z, accO[r][2]);
            accO[r][3] = fmaf(er[r], v4.w, accO[r][3]);
        }
    }

    const float4 sv4 = *(const float4*)&g_sv[coff + d0];
#pragma unroll
    for (int r = 0; r < 8; r++) {
        const int i = i0 + r;
        const float riv = rowinv[i];
        float4 o;
        o.x = (accO[r][0] + sv4.x) * riv;
        o.y = (accO[r][1] + sv4.y) * riv;
        o.z = (accO[r][2] + sv4.z) * riv;
        o.w = (accO[r][3] + sv4.w) * riv;
        __nv_bfloat16 hx = __float2bfloat16(o.x), hy = __float2bfloat16(o.y);
        __nv_bfloat16 hz = __float2bfloat16(o.z), hw = __float2bfloat16(o.w);
        const int base = ((t0 + i) * E_DIM + coff + d0) >> 1;
        __nv_bfloat162* H = (__nv_bfloat162*)g_ahi;
        __nv_bfloat162* L = (__nv_bfloat162*)g_alo;
        H[base + 0] = __nv_bfloat162{hx, hy};
        H[base + 1] = __nv_bfloat162{hz, hw};
        L[base + 0] = __nv_bfloat162{__float2bfloat16(o.x - __bfloat162float(hx)),
                                     __float2bfloat16(o.y - __bfloat162float(hy))};
        L[base + 1] = __nv_bfloat162{__float2bfloat16(o.z - __bfloat162float(hz)),
                                     __float2bfloat16(o.w - __bfloat162float(hw))};
    }
}

// ---------------- CEMA: chunked linear scan ----------------
__global__ void __launch_bounds__(128)
cema_pass1(const float* __restrict__ x, const float* __restrict__ p_coeff,
           const float* __restrict__ q_coeff, const float* __restrict__ gamma)
{
    const int gid  = blockIdx.x * 128 + threadIdx.x;
    const int e    = gid & 511;
    const int chnk = gid >> 9;
    float p[NDIMS], q[NDIMS], g[NDIMS], h[NDIMS];
#pragma unroll
    for (int d = 0; d < NDIMS; d++) {
        p[d] = p_coeff[e * NDIMS + d];
        q[d] = q_coeff[e * NDIMS + d];
        g[d] = gamma  [e * NDIMS + d];
        h[d] = 0.f;
    }
    const int tbase = chnk * CLEN;
    for (int t = 0; t < CLEN; t++) {
        const float xv = x[(tbase + t) * E_DIM + e];
        float y = 0.f;
#pragma unroll
        for (int d = 0; d < NDIMS; d++) {
            h[d] = fmaf(q[d], h[d], p[d] * xv);
            y    = fmaf(g[d], h[d], y);
        }
        g_cema[(tbase + t) * E_DIM + e] = y;
    }
#pragma unroll
    for (int d = 0; d < NDIMS; d++)
        g_hend[chnk * (E_DIM * NDIMS) + e * NDIMS + d] = h[d];
}

__global__ void __launch_bounds__(128)
cema_carry(const float* __restrict__ q_coeff)
{
    const int gid = blockIdx.x * 128 + threadIdx.x;
    const float q = q_coeff[gid];
    float qc = q;
#pragma unroll
    for (int i = 0; i < 6; i++) qc *= qc;              // q^64
    float G = 0.f;
    for (int c = 0; c < CHUNKS; c++) {
        g_carry[c * (E_DIM * NDIMS) + gid] = G;
        G = fmaf(qc, G, g_hend[c * (E_DIM * NDIMS) + gid]);
    }
}

__global__ void __launch_bounds__(128)
cema_pass2(const float* __restrict__ q_coeff, const float* __restrict__ gamma)
{
    const int gid  = blockIdx.x * 128 + threadIdx.x;
    const int e    = gid & 511;
    const int chnk = gid >> 9;
    if (chnk == 0) return;
    float q[NDIMS], w[NDIMS];
#pragma unroll
    for (int d = 0; d < NDIMS; d++) {
        q[d] = q_coeff[e * NDIMS + d];
        w[d] = gamma[e * NDIMS + d] * g_carry[chnk * (E_DIM * NDIMS) + e * NDIMS + d];
    }
    const int tbase = chnk * CLEN;
    for (int t = 0; t < CLEN; t++) {
        float y = 0.f;
#pragma unroll
        for (int d = 0; d < NDIMS; d++) {
            w[d] *= q[d];
            y    += w[d];
        }
        g_cema[(tbase + t) * E_DIM + e] += y;
    }
}

// ---------------------------- launch ----------------------------
extern "C" void kernel_launch(void* const* d_in, const int* in_sizes, int n_in,
                              void* d_out, int out_size)
{
    (void)in_sizes; (void)n_in; (void)out_size;
    const float* x       = (const float*)d_in[0];
    const float* W_qkv   = (const float*)d_in[1];
    const float* b_qkv   = (const float*)d_in[2];
    const float* W_out   = (const float*)d_in[3];
    const float* b_out   = (const float*)d_in[4];
    const float* p_coeff = (const float*)d_in[6];
    const float* q_coeff = (const float*)d_in[7];
    const float* gamma   = (const float*)d_in[8];
    const float* aw      = (const float*)d_in[9];
    float* out = (float*)d_out;

    float *qkvp, *cemap, *svp;
    __nv_bfloat16 *xhi, *xlo, *ahi, *alo, *wqh, *wql, *woh, *wol;
    cudaGetSymbolAddress((void**)&qkvp,  g_qkv);
    cudaGetSymbolAddress((void**)&cemap, g_cema);
    cudaGetSymbolAddress((void**)&svp,   g_sv);
    cudaGetSymbolAddress((void**)&xhi, g_xhi);
    cudaGetSymbolAddress((void**)&xlo, g_xlo);
    cudaGetSymbolAddress((void**)&ahi, g_ahi);
    cudaGetSymbolAddress((void**)&alo, g_alo);
    cudaGetSymbolAddress((void**)&wqh, g_wqT_hi);
    cudaGetSymbolAddress((void**)&wql, g_wqT_lo);
    cudaGetSymbolAddress((void**)&woh, g_woT_hi);
    cudaGetSymbolAddress((void**)&wol, g_woT_lo);

    cudaFuncSetAttribute(gemm_mma, cudaFuncAttributeMaxDynamicSharedMemorySize, GEMM_SMEM_BYTES);
    cudaFuncSetAttribute(attn_kernel, cudaFuncAttributeMaxDynamicSharedMemorySize,
                         ATTN_SMEM_FLOATS * (int)sizeof(float));

    // one-time host-object setup (first call is uncaptured; streams/events are
    // host-side objects, no device memory involved)
    static cudaStream_t s_side = nullptr;
    static cudaEvent_t  s_fork = nullptr, s_join = nullptr;
    if (s_side == nullptr) {
        cudaStreamCreateWithFlags(&s_side, cudaStreamNonBlocking);
        cudaEventCreateWithFlags(&s_fork, cudaEventDisableTiming);
        cudaEventCreateWithFlags(&s_join, cudaEventDisableTiming);
    }

    // ---- fork: CEMA chain + W_out transpose run concurrently on side stream
    cudaEventRecord(s_fork, 0);
    cudaStreamWaitEvent(s_side, s_fork, 0);

    cema_pass1<<<(E_DIM * CHUNKS) / 128, 128, 0, s_side>>>(x, p_coeff, q_coeff, gamma);
    cema_carry<<<(E_DIM * NDIMS) / 128, 128, 0, s_side>>>(q_coeff);
    cema_pass2<<<(E_DIM * CHUNKS) / 128, 128, 0, s_side>>>(q_coeff, gamma);
    transpose_conv<<<dim3(E_DIM / 32, E_DIM / 32), dim3(32, 8), 0, s_side>>>(
        W_out, woh, wol, E_DIM, E_DIM);
    cudaEventRecord(s_join, s_side);

    // ---- main stream: prep -> gemm1 -> sv -> attn
    cudaMemsetAsync(svp, 0, E_DIM * sizeof(float));
    conv_hilo<<<(N_TOK * E_DIM / 4) / 256, 256>>>(x, xhi, xlo);
    transpose_conv<<<dim3(QKV_LD / 32, E_DIM / 32), dim3(32, 8)>>>(W_qkv, wqh, wql, E_DIM, QKV_LD);

    gemm_mma<<<dim3(QKV_LD / 128, N_TOK / 64), 128, GEMM_SMEM_BYTES>>>(
        xhi, xlo, wqh, wql, b_qkv, qkvp, QKV_LD, 0, nullptr, nullptr);

    sv_kernel<<<NBLK, E_DIM>>>();
    attn_kernel<<<NH * NBLK, 256, ATTN_SMEM_FLOATS * (int)sizeof(float)>>>();

    // ---- join, then final fused GEMM
    cudaStreamWaitEvent(0, s_join, 0);
    gemm_mma<<<dim3(E_DIM / 128, N_TOK / 64), 128, GEMM_SMEM_BYTES>>>(
        ahi, alo, woh, wol, b_out, out, E_DIM, 1, cemap, aw);
}

// round 10
// speedup vs baseline: 2.0740x; 1.0302x over previous
#include <cuda_runtime.h>
#include <cuda_bf16.h>
#include <cmath>
#include <cstdint>

#define N_TOK 4096
#define E_DIM 512
#define NH 8
#define DK 64
#define WSZ 128
#define NBLK 32
#define NDIMS 16
#define QKV_LD 1536
#define CHUNKS 64
#define CLEN 64
#define KDIM 512

// ---------------- scratch (device globals) ----------------
__device__ float g_qkv [N_TOK * QKV_LD];
__device__ float g_cema[N_TOK * E_DIM];
__device__ float g_hend [CHUNKS * E_DIM * NDIMS];
__device__ float g_carry[CHUNKS * E_DIM * NDIMS];
__device__ float g_sv[E_DIM];
__device__ float g_xsum[E_DIM];
__device__ __nv_bfloat16 g_xhi [N_TOK * E_DIM];
__device__ __nv_bfloat16 g_xlo [N_TOK * E_DIM];
__device__ __nv_bfloat16 g_ahi [N_TOK * E_DIM];
__device__ __nv_bfloat16 g_alo [N_TOK * E_DIM];
__device__ __nv_bfloat16 g_wqT_hi[QKV_LD * E_DIM];
__device__ __nv_bfloat16 g_wqT_lo[QKV_LD * E_DIM];
__device__ __nv_bfloat16 g_woT_hi[E_DIM * E_DIM];
__device__ __nv_bfloat16 g_woT_lo[E_DIM * E_DIM];

// ---------------- PTX helpers ----------------
__device__ __forceinline__ uint32_t smem_u32(const void* p) {
    uint32_t a;
    asm("{ .reg .u64 t; cvta.to.shared.u64 t, %1; cvt.u32.u64 %0, t; }" : "=r"(a) : "l"(p));
    return a;
}
__device__ __forceinline__ void ldsm_x4(uint32_t* r, uint32_t addr) {
    asm volatile("ldmatrix.sync.aligned.m8n8.x4.shared.b16 {%0,%1,%2,%3}, [%4];"
        : "=r"(r[0]), "=r"(r[1]), "=r"(r[2]), "=r"(r[3]) : "r"(addr));
}
__device__ __forceinline__ void ldsm_x2(uint32_t* r, uint32_t addr) {
    asm volatile("ldmatrix.sync.aligned.m8n8.x2.shared.b16 {%0,%1}, [%2];"
        : "=r"(r[0]), "=r"(r[1]) : "r"(addr));
}
__device__ __forceinline__ void mma_bf16(float* d, const uint32_t* a, const uint32_t* b) {
    asm volatile("mma.sync.aligned.m16n8k16.row.col.f32.bf16.bf16.f32 "
        "{%0,%1,%2,%3}, {%4,%5,%6,%7}, {%8,%9}, {%0,%1,%2,%3};"
        : "+f"(d[0]), "+f"(d[1]), "+f"(d[2]), "+f"(d[3])
        : "r"(a[0]), "r"(a[1]), "r"(a[2]), "r"(a[3]), "r"(b[0]), "r"(b[1]));
}
#define CP_ASYNC16(dst, src) \
    asm volatile("cp.async.cg.shared.global [%0], [%1], 16;" :: "r"(dst), "l"(src))
#define CP_COMMIT()  asm volatile("cp.async.commit_group;" ::: "memory")
#define CP_WAIT_1()  asm volatile("cp.async.wait_group 1;" ::: "memory")
#define CP_WAIT_0()  asm volatile("cp.async.wait_group 0;" ::: "memory")

// ---------------- prep kernels ----------------
__global__ void conv_hilo(const float* __restrict__ X,
                          __nv_bfloat16* __restrict__ hi, __nv_bfloat16* __restrict__ lo)
{
    const int i = blockIdx.x * blockDim.x + threadIdx.x;   // per float4
    float4 v = ((const float4*)X)[i];
    __nv_bfloat16 hx = __float2bfloat16(v.x), hy = __float2bfloat16(v.y);
    __nv_bfloat16 hz = __float2bfloat16(v.z), hw = __float2bfloat16(v.w);
    __nv_bfloat162* H = (__nv_bfloat162*)hi;
    __nv_bfloat162* L = (__nv_bfloat162*)lo;
    H[i * 2 + 0] = __nv_bfloat162{hx, hy};
    H[i * 2 + 1] = __nv_bfloat162{hz, hw};
    L[i * 2 + 0] = __nv_bfloat162{__float2bfloat16(v.x - __bfloat162float(hx)),
                                  __float2bfloat16(v.y - __bfloat162float(hy))};
    L[i * 2 + 1] = __nv_bfloat162{__float2bfloat16(v.z - __bfloat162float(hz)),
                                  __float2bfloat16(v.w - __bfloat162float(hw))};
}

// W [Kdim x Ndim] fp32 -> WT [Ndim x Kdim] bf16 hi/lo
__global__ void transpose_conv(const float* __restrict__ W,
                               __nv_bfloat16* __restrict__ Thi, __nv_bfloat16* __restrict__ Tlo,
                               int Kdim, int Ndim)
{
    __shared__ float t[32][33];
    const int n0 = blockIdx.x * 32, k0 = blockIdx.y * 32;
    const int tx = threadIdx.x, ty = threadIdx.y;
#pragma unroll
    for (int s = 0; s < 32; s += 8)
        t[ty + s][tx] = W[(k0 + ty + s) * Ndim + n0 + tx];
    __syncthreads();
#pragma unroll
    for (int s = 0; s < 32; s += 8) {
        float v = t[tx][ty + s];
        __nv_bfloat16 h = __float2bfloat16(v);
        Thi[(n0 + ty + s) * Kdim + k0 + tx] = h;
        Tlo[(n0 + ty + s) * Kdim + k0 + tx] = __float2bfloat16(v - __bfloat162float(h));
    }
}

// ---------------- S_v = (sum_t x_t) @ W_v + 4096*b_v (independent of gemm1) ----------------
__global__ void xsum_kernel(const float* __restrict__ x)
{
    const int c  = threadIdx.x;              // 512
    const int t0 = blockIdx.x * 128;
    float s = 0.f;
#pragma unroll 4
    for (int t = t0; t < t0 + 128; t++)
        s += x[t * E_DIM + c];
    atomicAdd(&g_xsum[c], s);
}

__global__ void sv_gemv(const float* __restrict__ W_qkv, const float* __restrict__ b_qkv)
{
    __shared__ float xs[E_DIM];
    const int c = threadIdx.x;               // 512
    xs[c] = g_xsum[c];
    __syncthreads();
    float s = 4096.f * b_qkv[2 * E_DIM + c];
    for (int e = 0; e < E_DIM; e++)
        s = fmaf(xs[e], W_qkv[e * QKV_LD + 2 * E_DIM + c], s);
    g_sv[c] = s;
}

// ---------------- bf16x3 tensor-core GEMM (R5 config + m_base) ----------------
#define KC 32
#define NCH (KDIM / KC)
#define LDSB 80
#define ST_AH 0
#define ST_AL 5120
#define ST_BH 10240
#define ST_BL 20480
#define STAGE_B 30720
#define GEMM_SMEM_BYTES (2 * STAGE_B)

__device__ __forceinline__ void gemm_load_chunk(
    uint32_t stage_sb, const __nv_bfloat16* Ahi, const __nv_bfloat16* Alo,
    const __nv_bfloat16* Bhi, const __nv_bfloat16* Blo,
    int m0, int n0, int kb, int tid)
{
#pragma unroll
    for (int i = 0; i < 2; i++) {                    // A: 64 rows x 4 segs
        const int idx = tid + i * 128;
        const int r = idx >> 2, seg = idx & 3;
        const uint32_t so = stage_sb + (uint32_t)(r * LDSB + seg * 16);
        const long ga = (long)(m0 + r) * KDIM + kb + seg * 8;
        CP_ASYNC16(so + ST_AH, Ahi + ga);
        CP_ASYNC16(so + ST_AL, Alo + ga);
    }
#pragma unroll
    for (int i = 0; i < 4; i++) {                    // B: 128 rows x 4 segs
        const int idx = tid + i * 128;
        const int r = idx >> 2, seg = idx & 3;
        const uint32_t so = stage_sb + (uint32_t)(r * LDSB + seg * 16);
        const long gb = (long)(n0 + r) * KDIM + kb + seg * 8;
        CP_ASYNC16(so + ST_BH, Bhi + gb);
        CP_ASYNC16(so + ST_BL, Blo + gb);
    }
}

__global__ void __launch_bounds__(128, 3)
gemm_mma(const __nv_bfloat16* __restrict__ Ahi, const __nv_bfloat16* __restrict__ Alo,
         const __nv_bfloat16* __restrict__ Bhi, const __nv_bfloat16* __restrict__ Blo,
         const float* __restrict__ bias, float* __restrict__ C, int ldc, int mode,
         int m_base,
         const float* __restrict__ cema, const float* __restrict__ aw)
{
    extern __shared__ __align__(16) char smem[];
    const uint32_t sb = smem_u32(smem);
    const int tid = threadIdx.x;
    const int wn = tid >> 5, lane = tid & 31;
    const int m0 = m_base + blockIdx.y * 64, n0 = blockIdx.x * 128;

    const uint32_t a_off = (uint32_t)(lane & 15) * LDSB + ((lane >> 4) << 4);
    const uint32_t b_off = (uint32_t)(wn * 32 + (lane & 7)) * LDSB + (((lane >> 3) & 1) << 4);

    float acc[4][4][4];
#pragma unroll
    for (int mt = 0; mt < 4; mt++)
#pragma unroll
        for (int nt = 0; nt < 4; nt++)
#pragma unroll
            for (int c = 0; c < 4; c++) acc[mt][nt][c] = 0.f;

    gemm_load_chunk(sb, Ahi, Alo, Bhi, Blo, m0, n0, 0, tid);
    CP_COMMIT();

    for (int ch = 0; ch < NCH; ch++) {
        const uint32_t st = sb + (uint32_t)((ch & 1) * STAGE_B);
        if (ch + 1 < NCH) {
            gemm_load_chunk(sb + (uint32_t)(((ch + 1) & 1) * STAGE_B),
                            Ahi, Alo, Bhi, Blo, m0, n0, (ch + 1) * KC, tid);
            CP_COMMIT();
            CP_WAIT_1();
        } else {
            CP_WAIT_0();
        }
        __syncthreads();

#pragma unroll
        for (int ks = 0; ks < 2; ks++) {
            const uint32_t kofs = ks * 32;
            uint32_t bh[4][2], bl[4][2];
#pragma unroll
            for (int nt = 0; nt < 4; nt++) {
                ldsm_x2(bh[nt], st + ST_BH + b_off + nt * (8 * LDSB) + kofs);
                ldsm_x2(bl[nt], st + ST_BL + b_off + nt * (8 * LDSB) + kofs);
            }
#pragma unroll
            for (int mt = 0; mt < 4; mt++) {
                uint32_t ah[4], al[4];
                ldsm_x4(ah, st + ST_AH + a_off + mt * (16 * LDSB) + kofs);
                ldsm_x4(al, st + ST_AL + a_off + mt * (16 * LDSB) + kofs);
#pragma unroll
                for (int nt = 0; nt < 4; nt++) {
                    mma_bf16(acc[mt][nt], ah, bh[nt]);
                    mma_bf16(acc[mt][nt], ah, bl[nt]);
                    mma_bf16(acc[mt][nt], al, bh[nt]);
                }
            }
        }
        __syncthreads();
    }

    float w0 = 1.f, w1 = 0.f;
    if (mode == 1) {
        float a0 = aw[0], a1 = aw[1];
        float mx = fmaxf(a0, a1);
        float e0 = expf(a0 - mx), e1 = expf(a1 - mx);
        float inv = 1.f / (e0 + e1);
        w0 = e0 * inv; w1 = e1 * inv;
    }

#pragma unroll
    for (int mt = 0; mt < 4; mt++) {
        const int r0 = m0 + mt * 16 + (lane >> 2);
#pragma unroll
        for (int nt = 0; nt < 4; nt++) {
            const int col = n0 + wn * 32 + nt * 8 + (lane & 3) * 2;
            const float b0v = bias[col], b1v = bias[col + 1];
            float2 v0 = make_float2(acc[mt][nt][0] + b0v, acc[mt][nt][1] + b1v);
            float2 v1 = make_float2(acc[mt][nt][2] + b0v, acc[mt][nt][3] + b1v);
            if (mode == 1) {
                float2 c0 = *(const float2*)&cema[r0 * ldc + col];
                float2 c1 = *(const float2*)&cema[(r0 + 8) * ldc + col];
                v0.x = fmaf(w0, v0.x, w1 * c0.x);  v0.y = fmaf(w0, v0.y, w1 * c0.y);
                v1.x = fmaf(w0, v1.x, w1 * c1.x);  v1.y = fmaf(w0, v1.y, w1 * c1.y);
            }
            *(float2*)&C[r0 * ldc + col]       = v0;
            *(float2*)&C[(r0 + 8) * ldc + col] = v1;
        }
    }
}

// ---------------- fused block-local attention (half-range) ----------------
#define ATTN_SMEM_FLOATS (16384 + 8192 + 128)

__global__ void __launch_bounds__(256)
attn_kernel(int blk_base)
{
    extern __shared__ float sm[];
    float* qv     = sm;
    float* ks     = sm + 8192;
    float* Est    = sm;
    float* vv     = sm + 16384;
    float* rowinv = sm + 16384 + 8192;

    const int tid = threadIdx.x;
    const int h   = blockIdx.x >> 4;            // grid = NH * 16
    const int blk = blk_base + (blockIdx.x & 15);
    const int t0  = blk * WSZ;
    const int coff = h * DK;

    for (int idx = tid; idx < 2048; idx += 256) {
        const int i = idx >> 4, d4 = (idx & 15) << 2;
        const float* src = &g_qkv[(t0 + i) * QKV_LD + coff + d4];
        float4 q4 = *(const float4*)src;
        float4 k4 = *(const float4*)(src + E_DIM);
        float4 v4 = *(const float4*)(src + 2 * E_DIM);
        qv[(d4 + 0) * 128 + i] = q4.x;  ks[(d4 + 0) * 128 + i] = k4.x;
        qv[(d4 + 1) * 128 + i] = q4.y;  ks[(d4 + 1) * 128 + i] = k4.y;
        qv[(d4 + 2) * 128 + i] = q4.z;  ks[(d4 + 2) * 128 + i] = k4.z;
        qv[(d4 + 3) * 128 + i] = q4.w;  ks[(d4 + 3) * 128 + i] = k4.w;
        *(float4*)&vv[i * 64 + d4] = v4;
    }
    __syncthreads();

    const int tx = tid & 15, ty = tid >> 4;
    const int ib = tx * 8, jb = ty * 8;
    float accS[8][8];
#pragma unroll
    for (int r = 0; r < 8; r++)
#pragma unroll
        for (int c = 0; c < 8; c++) accS[r][c] = 0.f;

#pragma unroll 4
    for (int d = 0; d < 64; d++) {
        float qr[8], kr[8];
        *(float4*)&qr[0] = *(const float4*)&qv[d * 128 + ib];
        *(float4*)&qr[4] = *(const float4*)&qv[d * 128 + ib + 4];
        *(float4*)&kr[0] = *(const float4*)&ks[d * 128 + jb];
        *(float4*)&kr[4] = *(const float4*)&ks[d * 128 + jb + 4];
#pragma unroll
        for (int r = 0; r < 8; r++)
#pragma unroll
            for (int c = 0; c < 8; c++)
                accS[r][c] = fmaf(qr[r], kr[c], accS[r][c]);
    }
    __syncthreads();

#pragma unroll
    for (int c = 0; c < 8; c++) {
        const int j = jb + c;
        float e[8];
#pragma unroll
        for (int r = 0; r < 8; r++) {
            const int i = ib + r;
            e[r] = (j <= i) ? (expf(accS[r][c] * 0.125f) - 1.0f) : 0.0f;
        }
        *(float4*)&Est[j * 128 + ib]     = make_float4(e[0], e[1], e[2], e[3]);
        *(float4*)&Est[j * 128 + ib + 4] = make_float4(e[4], e[5], e[6], e[7]);
    }
    __syncthreads();

    if (tid < 128) {
        float s = 0.f;
#pragma unroll 4
        for (int j = 0; j < 128; j++) s += Est[j * 128 + tid];
        rowinv[tid] = 1.0f / (s + 4096.0f);
    }
    __syncthreads();

    const int i0 = ty * 8, d0 = tx * 4;
    float accO[8][4];
#pragma unroll
    for (int r = 0; r < 8; r++)
#pragma unroll
        for (int c = 0; c < 4; c++) accO[r][c] = 0.f;

#pragma unroll 2
    for (int j = 0; j < 128; j++) {
        float er[8];
        *(float4*)&er[0] = *(const float4*)&Est[j * 128 + i0];
        *(float4*)&er[4] = *(const float4*)&Est[j * 128 + i0 + 4];
        float4 v4 = *(const float4*)&vv[j * 64 + d0];
#pragma unroll
        for (int r = 0; r < 8; r++) {
            accO[r][0] = fmaf(er[r], v4.x, accO[r][0]);
            accO[r][1] = fmaf(er[r], v4.y, accO[r][1]);
            accO[r][2] = fmaf(er[r], v4.z, accO[r][2]);
            accO[r][3] = fmaf(er[r], v4.w, accO[r][3]);
        }
    }

    const float4 sv4 = *(const float4*)&g_sv[coff + d0];
#pragma unroll
    for (int r = 0; r < 8; r++) {
        const int i = i0 + r;
        const float riv = rowinv[i];
        float4 o;
        o.x = (accO[r][0] + sv4.x) * riv;
        o.y = (accO[r][1] + sv4.y) * riv;
        o.z = (accO[r][2] + sv4.z) * riv;
        o.w = (accO[r][3] + sv4.w) * riv;
        __nv_bfloat16 hx = __float2bfloat16(o.x), hy = __float2bfloat16(o.y);
        __nv_bfloat16 hz = __float2bfloat16(o.z), hw = __float2bfloat16(o.w);
        const int base = ((t0 + i) * E_DIM + coff + d0) >> 1;
        __nv_bfloat162* H = (__nv_bfloat162*)g_ahi;
        __nv_bfloat162* L = (__nv_bfloat162*)g_alo;
        H[base + 0] = __nv_bfloat162{hx, hy};
        H[base + 1] = __nv_bfloat162{hz, hw};
        L[base + 0] = __nv_bfloat162{__float2bfloat16(o.x - __bfloat162float(hx)),
                                     __float2bfloat16(o.y - __bfloat162float(hy))};
        L[base + 1] = __nv_bfloat162{__float2bfloat16(o.z - __bfloat162float(hz)),
                                     __float2bfloat16(o.w - __bfloat162float(hw))};
    }
}

// ---------------- CEMA: chunked linear scan ----------------
__global__ void __launch_bounds__(128)
cema_pass1(const float* __restrict__ x, const float* __restrict__ p_coeff,
           const float* __restrict__ q_coeff, const float* __restrict__ gamma)
{
    const int gid  = blockIdx.x * 128 + threadIdx.x;
    const int e    = gid & 511;
    const int chnk = gid >> 9;
    float p[NDIMS], q[NDIMS], g[NDIMS], h[NDIMS];
#pragma unroll
    for (int d = 0; d < NDIMS; d++) {
        p[d] = p_coeff[e * NDIMS + d];
        q[d] = q_coeff[e * NDIMS + d];
        g[d] = gamma  [e * NDIMS + d];
        h[d] = 0.f;
    }
    const int tbase = chnk * CLEN;
    for (int t = 0; t < CLEN; t++) {
        const float xv = x[(tbase + t) * E_DIM + e];
        float y = 0.f;
#pragma unroll
        for (int d = 0; d < NDIMS; d++) {
            h[d] = fmaf(q[d], h[d], p[d] * xv);
            y    = fmaf(g[d], h[d], y);
        }
        g_cema[(tbase + t) * E_DIM + e] = y;
    }
#pragma unroll
    for (int d = 0; d < NDIMS; d++)
        g_hend[chnk * (E_DIM * NDIMS) + e * NDIMS + d] = h[d];
}

__global__ void __launch_bounds__(128)
cema_carry(const float* __restrict__ q_coeff)
{
    const int gid = blockIdx.x * 128 + threadIdx.x;
    const float q = q_coeff[gid];
    float qc = q;
#pragma unroll
    for (int i = 0; i < 6; i++) qc *= qc;              // q^64
    float G = 0.f;
    for (int c = 0; c < CHUNKS; c++) {
        g_carry[c * (E_DIM * NDIMS) + gid] = G;
        G = fmaf(qc, G, g_hend[c * (E_DIM * NDIMS) + gid]);
    }
}

__global__ void __launch_bounds__(128)
cema_pass2(const float* __restrict__ q_coeff, const float* __restrict__ gamma)
{
    const int gid  = blockIdx.x * 128 + threadIdx.x;
    const int e    = gid & 511;
    const int chnk = gid >> 9;
    if (chnk == 0) return;
    float q[NDIMS], w[NDIMS];
#pragma unroll
    for (int d = 0; d < NDIMS; d++) {
        q[d] = q_coeff[e * NDIMS + d];
        w[d] = gamma[e * NDIMS + d] * g_carry[chnk * (E_DIM * NDIMS) + e * NDIMS + d];
    }
    const int tbase = chnk * CLEN;
    for (int t = 0; t < CLEN; t++) {
        float y = 0.f;
#pragma unroll
        for (int d = 0; d < NDIMS; d++) {
            w[d] *= q[d];
            y    += w[d];
        }
        g_cema[(tbase + t) * E_DIM + e] += y;
    }
}

// ---------------------------- launch ----------------------------
extern "C" void kernel_launch(void* const* d_in, const int* in_sizes, int n_in,
                              void* d_out, int out_size)
{
    (void)in_sizes; (void)n_in; (void)out_size;
    const float* x       = (const float*)d_in[0];
    const float* W_qkv   = (const float*)d_in[1];
    const float* b_qkv   = (const float*)d_in[2];
    const float* W_out   = (const float*)d_in[3];
    const float* b_out   = (const float*)d_in[4];
    const float* p_coeff = (const float*)d_in[6];
    const float* q_coeff = (const float*)d_in[7];
    const float* gamma   = (const float*)d_in[8];
    const float* aw      = (const float*)d_in[9];
    float* out = (float*)d_out;

    float *qkvp, *cemap, *xsump;
    __nv_bfloat16 *xhi, *xlo, *ahi, *alo, *wqh, *wql, *woh, *wol;
    cudaGetSymbolAddress((void**)&qkvp,  g_qkv);
    cudaGetSymbolAddress((void**)&cemap, g_cema);
    cudaGetSymbolAddress((void**)&xsump, g_xsum);
    cudaGetSymbolAddress((void**)&xhi, g_xhi);
    cudaGetSymbolAddress((void**)&xlo, g_xlo);
    cudaGetSymbolAddress((void**)&ahi, g_ahi);
    cudaGetSymbolAddress((void**)&alo, g_alo);
    cudaGetSymbolAddress((void**)&wqh, g_wqT_hi);
    cudaGetSymbolAddress((void**)&wql, g_wqT_lo);
    cudaGetSymbolAddress((void**)&woh, g_woT_hi);
    cudaGetSymbolAddress((void**)&wol, g_woT_lo);

    cudaFuncSetAttribute(gemm_mma, cudaFuncAttributeMaxDynamicSharedMemorySize, GEMM_SMEM_BYTES);
    cudaFuncSetAttribute(attn_kernel, cudaFuncAttributeMaxDynamicSharedMemorySize,
                         ATTN_SMEM_FLOATS * (int)sizeof(float));

    // one-time host-object setup (host-side objects only)
    static cudaStream_t s_side = nullptr, s_attn = nullptr;
    static cudaEvent_t  e_fork = nullptr, e_sv = nullptr, e_g1a = nullptr,
                        e_attnA = nullptr, e_side = nullptr;
    if (s_side == nullptr) {
        cudaStreamCreateWithFlags(&s_side, cudaStreamNonBlocking);
        cudaStreamCreateWithFlags(&s_attn, cudaStreamNonBlocking);
        cudaEventCreateWithFlags(&e_fork,  cudaEventDisableTiming);
        cudaEventCreateWithFlags(&e_sv,    cudaEventDisableTiming);
        cudaEventCreateWithFlags(&e_g1a,   cudaEventDisableTiming);
        cudaEventCreateWithFlags(&e_attnA, cudaEventDisableTiming);
        cudaEventCreateWithFlags(&e_side,  cudaEventDisableTiming);
    }

    // ---- fork side stream: S_v (xsum + gemv), CEMA chain, W_out transpose
    cudaEventRecord(e_fork, 0);
    cudaStreamWaitEvent(s_side, e_fork, 0);

    cudaMemsetAsync(xsump, 0, E_DIM * sizeof(float), s_side);
    xsum_kernel<<<NBLK, E_DIM, 0, s_side>>>(x);
    sv_gemv<<<1, E_DIM, 0, s_side>>>(W_qkv, b_qkv);
    cudaEventRecord(e_sv, s_side);

    cema_pass1<<<(E_DIM * CHUNKS) / 128, 128, 0, s_side>>>(x, p_coeff, q_coeff, gamma);
    cema_carry<<<(E_DIM * NDIMS) / 128, 128, 0, s_side>>>(q_coeff);
    cema_pass2<<<(E_DIM * CHUNKS) / 128, 128, 0, s_side>>>(q_coeff, gamma);
    transpose_conv<<<dim3(E_DIM / 32, E_DIM / 32), dim3(32, 8), 0, s_side>>>(
        W_out, woh, wol, E_DIM, E_DIM);
    cudaEventRecord(e_side, s_side);

    // ---- main: prep -> gemm1 half A -> gemm1 half B
    conv_hilo<<<(N_TOK * E_DIM / 4) / 256, 256>>>(x, xhi, xlo);
    transpose_conv<<<dim3(QKV_LD / 32, E_DIM / 32), dim3(32, 8)>>>(W_qkv, wqh, wql, E_DIM, QKV_LD);

    gemm_mma<<<dim3(QKV_LD / 128, (N_TOK / 2) / 64), 128, GEMM_SMEM_BYTES>>>(
        xhi, xlo, wqh, wql, b_qkv, qkvp, QKV_LD, 0, 0, nullptr, nullptr);
    cudaEventRecord(e_g1a, 0);

    gemm_mma<<<dim3(QKV_LD / 128, (N_TOK / 2) / 64), 128, GEMM_SMEM_BYTES>>>(
        xhi, xlo, wqh, wql, b_qkv, qkvp, QKV_LD, 0, N_TOK / 2, nullptr, nullptr);

    // ---- attn half A on s_attn, concurrent with gemm1 half B
    cudaStreamWaitEvent(s_attn, e_g1a, 0);
    cudaStreamWaitEvent(s_attn, e_sv, 0);
    attn_kernel<<<NH * 16, 256, ATTN_SMEM_FLOATS * (int)sizeof(float), s_attn>>>(0);
    cudaEventRecord(e_attnA, s_attn);

    // ---- attn half B on main (after gemm1b; needs S_v too)
    cudaStreamWaitEvent(0, e_sv, 0);
    attn_kernel<<<NH * 16, 256, ATTN_SMEM_FLOATS * (int)sizeof(float)>>>(16);

    // ---- join everything, then fused output GEMM
    cudaStreamWaitEvent(0, e_attnA, 0);
    cudaStreamWaitEvent(0, e_side, 0);
    gemm_mma<<<dim3(E_DIM / 128, N_TOK / 64), 128, GEMM_SMEM_BYTES>>>(
        ahi, alo, woh, wol, b_out, out, E_DIM, 1, 0, cemap, aw);
}